// round 10
// baseline (speedup 1.0000x reference)
#include <cuda_runtime.h>
#include <cuda_bf16.h>
#include <math.h>

#define NN   4096
#define FF   256
#define ELLW 256
#define TBITS 19
#define TSIZE (1 << TBITS)
#define TMASK (TSIZE - 1)

// ---------------- scratch (device globals) ----------------
__device__ int   g_hkey[TSIZE];
__device__ float g_hval[TSIZE];
__device__ float g_deg[NN];
__device__ float g_dinv[NN];
__device__ int   g_cnt[NN];
__device__ int   g_col[NN * ELLW];
__device__ float g_lre[NN * ELLW];
__device__ float g_lim[NN * ELLW];
__device__ float g_Z1r[NN * FF], g_Z1i[NN * FF];
__device__ float g_Qr[NN * FF],  g_Qi[NN * FF];
__device__ float g_H1r[NN * FF], g_H1i[NN * FF];
__device__ float g_H2r[NN * FF], g_H2i[NN * FF];
__device__ float g_P[2 * NN * FF];           // P = Z1*W2 (Pr rows 0..4095, Pi rows 4096..8191)
__device__ float g_Cp[2 * NN * FF];          // C = Z0*W0' + Z1*W1 (raw, stacked re/im)
__device__ float g_W0p1[FF * FF];            // W1[0] - W1[2]
__device__ float g_W0p2[FF * FF];            // W2[0] - W2[2]

__device__ __forceinline__ unsigned hash_key(int key) {
    return ((unsigned)key * 2654435761u) >> (32 - TBITS);
}

// ---------------- graph build (R2-proven) ----------------
__global__ void zero_kernel() {
    int idx = blockIdx.x * blockDim.x + threadIdx.x;
    if (idx < TSIZE) { g_hkey[idx] = -1; g_hval[idx] = 0.f; }
    if (idx < NN)    { g_deg[idx] = 0.f; g_cnt[idx] = 0; }
}

__global__ void insert_kernel(const int* __restrict__ edges,
                              const float* __restrict__ w, int E) {
    int e = blockIdx.x * blockDim.x + threadIdx.x;
    if (e >= E) return;
    int r = edges[e];
    int c = edges[E + e];
    float we = w[e];
    atomicAdd(&g_deg[r], 0.5f * we);
    atomicAdd(&g_deg[c], 0.5f * we);
    int key = (r << 12) | c;
    unsigned h = hash_key(key) & TMASK;
    while (true) {
        int prev = atomicCAS(&g_hkey[h], -1, key);
        if (prev == -1 || prev == key) { atomicAdd(&g_hval[h], we); break; }
        h = (h + 1) & TMASK;
    }
}

__global__ void dinv_kernel() {
    int i = blockIdx.x * blockDim.x + threadIdx.x;
    if (i < NN) {
        float d = g_deg[i];
        if (d == 0.f) d = 1.f;
        g_dinv[i] = rsqrtf(d);
    }
}

__device__ __forceinline__ float hash_lookup(int key, bool* found) {
    unsigned h = hash_key(key) & TMASK;
    while (true) {
        int k = g_hkey[h];
        if (k == key) { *found = true; return g_hval[h]; }
        if (k == -1)  { *found = false; return 0.f; }
        h = (h + 1) & TMASK;
    }
}

__device__ __forceinline__ void ell_push(int r, int c, float lre, float lim) {
    int slot = atomicAdd(&g_cnt[r], 1);
    if (slot < ELLW) {
        g_col[r * ELLW + slot] = c;
        g_lre[r * ELLW + slot] = lre;
        g_lim[r * ELLW + slot] = lim;
    }
}

__global__ void emit_kernel(const float* __restrict__ qp) {
    int s = blockIdx.x * blockDim.x + threadIdx.x;
    if (s >= TSIZE) return;
    int key = g_hkey[s];
    if (key < 0) return;
    int i = key >> 12;
    int j = key & 4095;
    float a = g_hval[s];
    float q = __ldg(qp);
    if (i == j) {
        float di = g_dinv[i];
        ell_push(i, i, -di * di * a, 0.f);
        return;
    }
    bool found;
    float at = hash_lookup((j << 12) | i, &found);
    if (i > j && found) return;
    float asym = 0.5f * (a + at);
    float an = g_dinv[i] * asym * g_dinv[j];
    float th = 6.283185307179586f * q * (a - at);
    float sn, cs;
    sincosf(th, &sn, &cs);
    ell_push(i, j, -an * cs,  an * sn);
    ell_push(j, i, -an * cs, -an * sn);
}

// W0' = W[0] - W[2] for both layers
__global__ void wsub_kernel(const float* __restrict__ W1, const float* __restrict__ W2) {
    int idx = blockIdx.x * blockDim.x + threadIdx.x;
    if (idx < FF * FF) {
        g_W0p1[idx] = W1[idx] - W1[2 * FF * FF + idx];
        g_W0p2[idx] = W2[idx] - W2[2 * FF * FF + idx];
    }
}

// ---------------- spmm device body (R2-proven gather) ----------------
__device__ __forceinline__ void spmm_row_body(
        char* smem, int row, int t,
        const float* __restrict__ Xr, const float* __restrict__ Xi,
        const float* __restrict__ Sr, const float* __restrict__ Si,
        float* __restrict__ Yr, float* __restrict__ Yi) {
    int*   sc  = (int*)smem;
    float* slr = (float*)(smem + 1024);
    float* sli = (float*)(smem + 2048);
    int cnt = g_cnt[row];
    if (cnt > ELLW) cnt = ELLW;
    for (int k = t; k < cnt; k += 256) {
        sc [k] = g_col[row * ELLW + k];
        slr[k] = g_lre[row * ELLW + k];
        sli[k] = g_lim[row * ELLW + k];
    }
    __syncthreads();
    float ar = 0.f, ai = 0.f;
    #pragma unroll 4
    for (int k = 0; k < cnt; k++) {
        int   c  = sc[k];
        float lr = slr[k];
        float li = sli[k];
        float xr = __ldg(&Xr[c * FF + t]);
        float xi = __ldg(&Xi[c * FF + t]);
        ar = fmaf(lr, xr, ar);
        ar = fmaf(-li, xi, ar);
        ai = fmaf(lr, xi, ai);
        ai = fmaf(li, xr, ai);
    }
    int o = row * FF + t;
    if (Sr) {
        Yr[o] = 2.f * ar - Sr[o];
        Yi[o] = 2.f * ai - Si[o];
    } else {
        Yr[o] = ar;
        Yi[o] = ai;
    }
}

__global__ void spmm_kernel(const float* __restrict__ Xr, const float* __restrict__ Xi,
                            float* __restrict__ Yr, float* __restrict__ Yi) {
    __shared__ char smem[3072];
    spmm_row_body(smem, blockIdx.x, threadIdx.x, Xr, Xi, nullptr, nullptr, Yr, Yi);
}

// ---------------- GEMM machinery (R9-proven) ----------------
__device__ __forceinline__ unsigned pack_bf2(float x, float y) {
    __nv_bfloat162 t;
    t.x = __float2bfloat16_rn(x);
    t.y = __float2bfloat16_rn(y);
    return *reinterpret_cast<unsigned*>(&t);
}

#define MMA_BF16(d, a, b)                                                        \
    asm volatile("mma.sync.aligned.m16n8k16.row.col.f32.bf16.bf16.f32 "          \
                 "{%0,%1,%2,%3},{%4,%5,%6,%7},{%8,%9},{%0,%1,%2,%3};"            \
                 : "+f"(d[0]), "+f"(d[1]), "+f"(d[2]), "+f"(d[3])                 \
                 : "r"(a[0]), "r"(a[1]), "r"(a[2]), "r"(a[3]), "r"(b[0]), "r"(b[1]))

#define LDSM_X4(r, addr)                                                         \
    asm volatile("ldmatrix.sync.aligned.m8n8.x4.shared.b16 {%0,%1,%2,%3}, [%4];" \
                 : "=r"(r[0]), "=r"(r[1]), "=r"(r[2]), "=r"(r[3]) : "r"(addr) : "memory")

#define LDSM_X4_T(r, addr)                                                             \
    asm volatile("ldmatrix.sync.aligned.m8n8.x4.trans.shared.b16 {%0,%1,%2,%3}, [%4];" \
                 : "=r"(r[0]), "=r"(r[1]), "=r"(r[2]), "=r"(r[3]) : "r"(addr) : "memory")

#define AST 20
#define WST 36
#define GEMM_SMEM_BYTES ((2 * 128 * AST + 2 * 32 * WST) * 4)   // 29696

__device__ __forceinline__ void gemm_chunk(
        unsigned* ash, unsigned* asl, unsigned* wsh, unsigned* wsl,
        unsigned a_hi_base, unsigned a_lo_base, unsigned w_hi_base, unsigned w_lo_base,
        unsigned a_off, unsigned w_off,
        const float* __restrict__ Ap, const float* __restrict__ Wp,
        int mrow0, int n0, int kc, int tid, float acc[4][2][4]) {
    #pragma unroll
    for (int t = 0; t < 4; t++) {
        int idx = tid + t * 256;
        int r = idx >> 3;
        int c4 = (idx & 7) * 4;
        float4 v = *reinterpret_cast<const float4*>(&Ap[(mrow0 + r) * 256 + kc + c4]);
        float hx = __bfloat162float(__float2bfloat16_rn(v.x));
        float hy = __bfloat162float(__float2bfloat16_rn(v.y));
        float hz = __bfloat162float(__float2bfloat16_rn(v.z));
        float hw = __bfloat162float(__float2bfloat16_rn(v.w));
        int o = r * AST + (c4 >> 1);
        ash[o]     = pack_bf2(v.x, v.y);
        ash[o + 1] = pack_bf2(v.z, v.w);
        asl[o]     = pack_bf2(v.x - hx, v.y - hy);
        asl[o + 1] = pack_bf2(v.z - hz, v.w - hw);
    }
    #pragma unroll
    for (int t = 0; t < 2; t++) {
        int idx = tid + t * 256;
        int kk = idx >> 4;
        int n4 = (idx & 15) * 4;
        float4 v = *reinterpret_cast<const float4*>(&Wp[(kc + kk) * 256 + n0 + n4]);
        float hx = __bfloat162float(__float2bfloat16_rn(v.x));
        float hy = __bfloat162float(__float2bfloat16_rn(v.y));
        float hz = __bfloat162float(__float2bfloat16_rn(v.z));
        float hw = __bfloat162float(__float2bfloat16_rn(v.w));
        int o = kk * WST + (n4 >> 1);
        wsh[o]     = pack_bf2(v.x, v.y);
        wsh[o + 1] = pack_bf2(v.z, v.w);
        wsl[o]     = pack_bf2(v.x - hx, v.y - hy);
        wsl[o + 1] = pack_bf2(v.z - hz, v.w - hw);
    }
    __syncthreads();

    #pragma unroll
    for (int h = 0; h < 32; h += 16) {
        unsigned ah[4][4], al[4][4];
        #pragma unroll
        for (int mt = 0; mt < 4; mt++) {
            unsigned off = a_off + (mt * 16 * AST * 2 + h) * 2;
            LDSM_X4(ah[mt], a_hi_base + off);
            LDSM_X4(al[mt], a_lo_base + off);
        }
        unsigned bh4[4], bl4[4];
        {
            unsigned off = w_off + (h * WST * 2) * 2;
            LDSM_X4_T(bh4, w_hi_base + off);
            LDSM_X4_T(bl4, w_lo_base + off);
        }
        #pragma unroll
        for (int mt = 0; mt < 4; mt++) {
            #pragma unroll
            for (int nt = 0; nt < 2; nt++) {
                unsigned bh[2] = {bh4[nt * 2], bh4[nt * 2 + 1]};
                unsigned bl[2] = {bl4[nt * 2], bl4[nt * 2 + 1]};
                MMA_BF16(acc[mt][nt], ah[mt], bh);
                MMA_BF16(acc[mt][nt], ah[mt], bl);
                MMA_BF16(acc[mt][nt], al[mt], bh);
            }
        }
    }
    __syncthreads();
}

// ---------------- P-gemm: P = Z1 @ W[2]  (K=256, raw output) ----------------
__global__ void __launch_bounds__(256, 2)
pgemm_kernel(const float* __restrict__ A_r, const float* __restrict__ A_i,
             const float* __restrict__ W, float* __restrict__ P) {
    __shared__ unsigned ash[128 * AST], asl[128 * AST];
    __shared__ unsigned wsh[32 * WST],  wsl[32 * WST];

    int tid = threadIdx.x;
    int lane = tid & 31;
    int warp = tid >> 5;
    int wm = warp >> 2;
    int wn = warp & 3;
    int m0 = blockIdx.y * 128;
    int n0 = blockIdx.x * 64;
    bool isImag = (m0 >= 4096);
    int mrow0 = m0 & 4095;

    float acc[4][2][4];
    #pragma unroll
    for (int mt = 0; mt < 4; mt++)
        #pragma unroll
        for (int nt = 0; nt < 2; nt++)
            #pragma unroll
            for (int r = 0; r < 4; r++) acc[mt][nt][r] = 0.f;

    unsigned a_hi_base = (unsigned)__cvta_generic_to_shared(ash);
    unsigned a_lo_base = (unsigned)__cvta_generic_to_shared(asl);
    unsigned w_hi_base = (unsigned)__cvta_generic_to_shared(wsh);
    unsigned w_lo_base = (unsigned)__cvta_generic_to_shared(wsl);
    unsigned a_off = ((wm * 64 + (lane & 15)) * (AST * 2) + (lane >> 4) * 8) * 2;
    unsigned w_off = (((((lane >> 3) & 1) * 8 + (lane & 7)) * (WST * 2)) + wn * 16 + (lane >> 4) * 8) * 2;

    const float* Ap = isImag ? A_i : A_r;
    for (int ks = 0; ks < 8; ks++) {
        gemm_chunk(ash, asl, wsh, wsl, a_hi_base, a_lo_base, w_hi_base, w_lo_base,
                   a_off, w_off, Ap, W + 2 * FF * FF, mrow0, n0, ks * 32, tid, acc);
    }

    int g = lane >> 2, tig = lane & 3;
    #pragma unroll
    for (int mt = 0; mt < 4; mt++) {
        #pragma unroll
        for (int nt = 0; nt < 2; nt++) {
            int n = n0 + wn * 16 + nt * 8 + tig * 2;
            int ml0 = m0 + wm * 64 + mt * 16 + g;
            float* c0 = acc[mt][nt];
            *reinterpret_cast<float2*>(&P[ml0 * 256 + n])       = make_float2(c0[0], c0[1]);
            *reinterpret_cast<float2*>(&P[(ml0 + 8) * 256 + n]) = make_float2(c0[2], c0[3]);
        }
    }
}

// ---------------- mixed kernel: spmm2 (Q = L P) interleaved with C-gemm ----------------
// 4352 blocks = 17*256. Block p is a C-gemm tile iff p % 17 == 16 (tile t = p/17),
// else spmm row = p - p/17. Interleaving spreads gemm blocks across SMs.
__global__ void mixed_kernel(
        const float* __restrict__ P,                                    // spmm X (stacked re/im)
        const float* __restrict__ Z0r, const float* __restrict__ Z0i,   // gemm plane 0
        const float* __restrict__ Z1r, const float* __restrict__ Z1i,   // gemm plane 1
        const float* __restrict__ W0p, const float* __restrict__ W1p,   // W planes
        float* __restrict__ Qr, float* __restrict__ Qi,                 // spmm out
        float* __restrict__ Cp) {
    __shared__ char smem_u[GEMM_SMEM_BYTES];
    int tid = threadIdx.x;
    int p = blockIdx.x;

    if ((p % 17) != 16) {
        int row = p - p / 17;
        spmm_row_body(smem_u, row, tid, P, P + NN * FF, nullptr, nullptr, Qr, Qi);
        return;
    }

    // --- C-gemm tile: C = Z0 @ W0p + Z1 @ W1p  (K = 512, raw output) ---
    int t = p / 17;
    unsigned* ash = (unsigned*)smem_u;
    unsigned* asl = ash + 128 * AST;
    unsigned* wsh = asl + 128 * AST;
    unsigned* wsl = wsh + 32 * WST;

    int lane = tid & 31;
    int warp = tid >> 5;
    int wm = warp >> 2;
    int wn = warp & 3;
    int m0 = (t >> 2) * 128;
    int n0 = (t & 3) * 64;
    bool isImag = (m0 >= 4096);
    int mrow0 = m0 & 4095;

    float acc[4][2][4];
    #pragma unroll
    for (int mt = 0; mt < 4; mt++)
        #pragma unroll
        for (int nt = 0; nt < 2; nt++)
            #pragma unroll
            for (int r = 0; r < 4; r++) acc[mt][nt][r] = 0.f;

    unsigned a_hi_base = (unsigned)__cvta_generic_to_shared(ash);
    unsigned a_lo_base = (unsigned)__cvta_generic_to_shared(asl);
    unsigned w_hi_base = (unsigned)__cvta_generic_to_shared(wsh);
    unsigned w_lo_base = (unsigned)__cvta_generic_to_shared(wsl);
    unsigned a_off = ((wm * 64 + (lane & 15)) * (AST * 2) + (lane >> 4) * 8) * 2;
    unsigned w_off = (((((lane >> 3) & 1) * 8 + (lane & 7)) * (WST * 2)) + wn * 16 + (lane >> 4) * 8) * 2;

    for (int ks = 0; ks < 16; ks++) {
        int plane = ks >> 3;
        int kc = (ks & 7) * 32;
        const float* Ap = isImag ? (plane ? Z1i : Z0i) : (plane ? Z1r : Z0r);
        const float* Wp = plane ? W1p : W0p;
        gemm_chunk(ash, asl, wsh, wsl, a_hi_base, a_lo_base, w_hi_base, w_lo_base,
                   a_off, w_off, Ap, Wp, mrow0, n0, kc, tid, acc);
    }

    int g = lane >> 2, tig = lane & 3;
    #pragma unroll
    for (int mt = 0; mt < 4; mt++) {
        #pragma unroll
        for (int nt = 0; nt < 2; nt++) {
            int n = n0 + wn * 16 + nt * 8 + tig * 2;
            int ml0 = m0 + wm * 64 + mt * 16 + g;
            float* c0 = acc[mt][nt];
            *reinterpret_cast<float2*>(&Cp[ml0 * 256 + n])       = make_float2(c0[0], c0[1]);
            *reinterpret_cast<float2*>(&Cp[(ml0 + 8) * 256 + n]) = make_float2(c0[2], c0[3]);
        }
    }
}

// ---------------- elementwise combine: H = i(C + 2Q) + b ----------------
__global__ void elem_kernel(const float* __restrict__ Cp,
                            const float* __restrict__ Qr, const float* __restrict__ Qi,
                            const float* __restrict__ bias,
                            float* __restrict__ Hr, float* __restrict__ Hi) {
    int o = blockIdx.x * blockDim.x + threadIdx.x;   // 0 .. NN*FF-1
    int c = o & 255;
    float b = bias[c];
    float sre = Cp[o]           + 2.f * Qr[o];
    float sim = Cp[o + NN * FF] + 2.f * Qi[o];
    Hi[o] = sre + b;     // out_imag = S_re + b
    Hr[o] = -sim + b;    // out_real = -S_im + b
}

// ---------------- classifier + log_softmax (R2-proven) ----------------
__global__ void classifier_kernel(const float* __restrict__ Hr, const float* __restrict__ Hi,
                                  const float* __restrict__ Wc, const float* __restrict__ bc,
                                  float* __restrict__ out) {
    int row = blockIdx.x;
    int t = threadIdx.x;   // 128
    __shared__ float x[512];
    __shared__ float lg[40];
    for (int i = t; i < 256; i += 128) {
        x[i]       = Hr[row * 256 + i];
        x[i + 256] = Hi[row * 256 + i];
    }
    __syncthreads();
    int warp = t >> 5, lane = t & 31;
    for (int c = warp; c < 40; c += 4) {
        float s = 0.f;
        #pragma unroll
        for (int k = lane; k < 512; k += 32) s = fmaf(x[k], Wc[c * 512 + k], s);
        #pragma unroll
        for (int o = 16; o > 0; o >>= 1) s += __shfl_xor_sync(0xffffffffu, s, o);
        if (lane == 0) lg[c] = s + bc[c];
    }
    __syncthreads();
    if (warp == 0) {
        float a  = (lane < 40)      ? lg[lane]      : -3.4e38f;
        float b2 = (lane + 32 < 40) ? lg[lane + 32] : -3.4e38f;
        float m = fmaxf(a, b2);
        #pragma unroll
        for (int o = 16; o > 0; o >>= 1) m = fmaxf(m, __shfl_xor_sync(0xffffffffu, m, o));
        float s = ((lane < 40) ? expf(a - m) : 0.f) + ((lane + 32 < 40) ? expf(b2 - m) : 0.f);
        #pragma unroll
        for (int o = 16; o > 0; o >>= 1) s += __shfl_xor_sync(0xffffffffu, s, o);
        float lse = m + logf(s);
        if (lane < 40)      out[row * 40 + lane]      = a - lse;
        if (lane + 32 < 40) out[row * 40 + lane + 32] = b2 - lse;
    }
}

// ---------------- launch ----------------
extern "C" void kernel_launch(void* const* d_in, const int* in_sizes, int n_in,
                              void* d_out, int out_size) {
    const float* real = (const float*)d_in[0];
    const float* imag = (const float*)d_in[1];
    const int*   edges = (const int*)d_in[2];
    const float* qp = (const float*)d_in[3];
    const float* ew = (const float*)d_in[4];
    const float* W1 = (const float*)d_in[5];
    const float* b1 = (const float*)d_in[6];
    const float* W2 = (const float*)d_in[7];
    const float* b2 = (const float*)d_in[8];
    const float* Wc = (const float*)d_in[9];
    const float* bc = (const float*)d_in[10];
    float* out = (float*)d_out;
    int E = in_sizes[4];

    float *Z1r, *Z1i, *Qr, *Qi, *H1r, *H1i, *H2r, *H2i, *P, *Cp, *W0p1, *W0p2;
    cudaGetSymbolAddress((void**)&Z1r, g_Z1r);
    cudaGetSymbolAddress((void**)&Z1i, g_Z1i);
    cudaGetSymbolAddress((void**)&Qr,  g_Qr);
    cudaGetSymbolAddress((void**)&Qi,  g_Qi);
    cudaGetSymbolAddress((void**)&H1r, g_H1r);
    cudaGetSymbolAddress((void**)&H1i, g_H1i);
    cudaGetSymbolAddress((void**)&H2r, g_H2r);
    cudaGetSymbolAddress((void**)&H2i, g_H2i);
    cudaGetSymbolAddress((void**)&P,   g_P);
    cudaGetSymbolAddress((void**)&Cp,  g_Cp);
    cudaGetSymbolAddress((void**)&W0p1, g_W0p1);
    cudaGetSymbolAddress((void**)&W0p2, g_W0p2);

    // graph build
    zero_kernel<<<TSIZE / 256, 256>>>();
    insert_kernel<<<(E + 255) / 256, 256>>>(edges, ew, E);
    dinv_kernel<<<NN / 256, 256>>>();
    emit_kernel<<<TSIZE / 256, 256>>>(qp);
    wsub_kernel<<<(FF * FF) / 256, 256>>>(W1, W2);

    // ---- layer 1 ----
    spmm_kernel<<<NN, 256>>>(real, imag, Z1r, Z1i);                       // Z1 = L X
    pgemm_kernel<<<dim3(4, 64), 256>>>(Z1r, Z1i, W1, P);                  // P = Z1 W1[2]
    mixed_kernel<<<17 * 256, 256>>>(P, real, imag, Z1r, Z1i,
                                    W0p1, W1 + FF * FF, Qr, Qi, Cp);      // Q = L P || C
    elem_kernel<<<NN, 256>>>(Cp, Qr, Qi, b1, H1r, H1i);                   // H1 = i(C+2Q)+b

    // ---- layer 2 ----
    spmm_kernel<<<NN, 256>>>(H1r, H1i, Z1r, Z1i);
    pgemm_kernel<<<dim3(4, 64), 256>>>(Z1r, Z1i, W2, P);
    mixed_kernel<<<17 * 256, 256>>>(P, H1r, H1i, Z1r, Z1i,
                                    W0p2, W2 + FF * FF, Qr, Qi, Cp);
    elem_kernel<<<NN, 256>>>(Cp, Qr, Qi, b2, H2r, H2i);

    classifier_kernel<<<NN, 128>>>(H2r, H2i, Wc, bc, out);
}

// round 11
// speedup vs baseline: 1.2072x; 1.2072x over previous
#include <cuda_runtime.h>
#include <cuda_bf16.h>
#include <math.h>

#define NN   4096
#define FF   256
#define ELLW 256
#define TBITS 19
#define TSIZE (1 << TBITS)
#define TMASK (TSIZE - 1)

// ---------------- scratch (device globals) ----------------
__device__ int   g_hkey[TSIZE];
__device__ float g_hval[TSIZE];
__device__ float g_deg[NN];
__device__ float g_dinv[NN];
__device__ int   g_cnt[NN];
__device__ int   g_col[NN * ELLW];
__device__ float g_lre[NN * ELLW];
__device__ float g_lim[NN * ELLW];
__device__ float g_Z1r[NN * FF], g_Z1i[NN * FF];
__device__ float g_Z2r[NN * FF], g_Z2i[NN * FF];
__device__ float g_H1r[NN * FF], g_H1i[NN * FF];
__device__ float g_H2r[NN * FF], g_H2i[NN * FF];

__device__ __forceinline__ unsigned hash_key(int key) {
    return ((unsigned)key * 2654435761u) >> (32 - TBITS);
}

// ---------------- graph build (hash-based, no dense A) ----------------
__global__ void zero_kernel() {
    int idx = blockIdx.x * blockDim.x + threadIdx.x;
    if (idx < TSIZE) { g_hkey[idx] = -1; g_hval[idx] = 0.f; }
    if (idx < NN)    { g_deg[idx] = 0.f; g_cnt[idx] = 0; }
}

__global__ void insert_kernel(const int* __restrict__ edges,
                              const float* __restrict__ w, int E) {
    int e = blockIdx.x * blockDim.x + threadIdx.x;
    if (e >= E) return;
    int r = edges[e];
    int c = edges[E + e];
    float we = w[e];
    atomicAdd(&g_deg[r], 0.5f * we);
    atomicAdd(&g_deg[c], 0.5f * we);
    int key = (r << 12) | c;
    unsigned h = hash_key(key) & TMASK;
    while (true) {
        int prev = atomicCAS(&g_hkey[h], -1, key);
        if (prev == -1 || prev == key) { atomicAdd(&g_hval[h], we); break; }
        h = (h + 1) & TMASK;
    }
}

__global__ void dinv_kernel() {
    int i = blockIdx.x * blockDim.x + threadIdx.x;
    if (i < NN) {
        float d = g_deg[i];
        if (d == 0.f) d = 1.f;
        g_dinv[i] = rsqrtf(d);
    }
}

__device__ __forceinline__ float hash_lookup(int key, bool* found) {
    unsigned h = hash_key(key) & TMASK;
    while (true) {
        int k = g_hkey[h];
        if (k == key) { *found = true; return g_hval[h]; }
        if (k == -1)  { *found = false; return 0.f; }
        h = (h + 1) & TMASK;
    }
}

__device__ __forceinline__ void ell_push(int r, int c, float lre, float lim) {
    int slot = atomicAdd(&g_cnt[r], 1);
    if (slot < ELLW) {
        g_col[r * ELLW + slot] = c;
        g_lre[r * ELLW + slot] = lre;
        g_lim[r * ELLW + slot] = lim;
    }
}

__global__ void emit_kernel(const float* __restrict__ qp) {
    int s = blockIdx.x * blockDim.x + threadIdx.x;
    if (s >= TSIZE) return;
    int key = g_hkey[s];
    if (key < 0) return;
    int i = key >> 12;
    int j = key & 4095;
    float a = g_hval[s];
    float q = __ldg(qp);
    if (i == j) {
        float di = g_dinv[i];
        float an = di * di * a;
        ell_push(i, i, -an, 0.f);
        return;
    }
    bool found;
    float at = hash_lookup((j << 12) | i, &found);
    if (i > j && found) return;   // handled by the (j,i) slot
    float asym = 0.5f * (a + at);
    float an = g_dinv[i] * asym * g_dinv[j];
    float th = 6.283185307179586f * q * (a - at);
    float sn, cs;
    sincosf(th, &sn, &cs);
    // conj(L)[i][j] = -A_n * exp(-i*th)  -> ( -an*cs , +an*sn )
    ell_push(i, j, -an * cs,  an * sn);
    ell_push(j, i, -an * cs, -an * sn);
}

// ---------------- complex SpMM (ELL) ----------------
__global__ void spmm_kernel(const float* __restrict__ Xr, const float* __restrict__ Xi,
                            const float* __restrict__ Sr, const float* __restrict__ Si,
                            float* __restrict__ Yr, float* __restrict__ Yi) {
    int row = blockIdx.x;
    int t = threadIdx.x;
    int cnt = g_cnt[row];
    if (cnt > ELLW) cnt = ELLW;
    __shared__ int   sc[ELLW];
    __shared__ float slr[ELLW];
    __shared__ float sli[ELLW];
    for (int k = t; k < cnt; k += 256) {
        sc [k] = g_col[row * ELLW + k];
        slr[k] = g_lre[row * ELLW + k];
        sli[k] = g_lim[row * ELLW + k];
    }
    __syncthreads();
    float ar = 0.f, ai = 0.f;
    #pragma unroll 4
    for (int k = 0; k < cnt; k++) {
        int   c  = sc[k];
        float lr = slr[k];
        float li = sli[k];
        float xr = __ldg(&Xr[c * FF + t]);
        float xi = __ldg(&Xi[c * FF + t]);
        ar = fmaf(lr, xr, ar);
        ar = fmaf(-li, xi, ar);
        ai = fmaf(lr, xi, ai);
        ai = fmaf(li, xr, ai);
    }
    int o = row * FF + t;
    if (Sr) {
        Yr[o] = 2.f * ar - Sr[o];
        Yi[o] = 2.f * ai - Si[o];
    } else {
        Yr[o] = ar;
        Yi[o] = ai;
    }
}

// ---------------- fused tensor-core GEMM (bf16 3-term split) ----------------
// C[8192,256] = [Zr;Zi](8192x768) @ Wcat(768x256); rows<4096 -> Hi=C+b, rows>=4096 -> Hr=-C+b
// BM=128, BN=64, BK=32; 256 thr = 8 warps (2m x 4n); warp tile 64x16.

__device__ __forceinline__ unsigned pack_bf2(float x, float y) {
    __nv_bfloat162 t;
    t.x = __float2bfloat16_rn(x);
    t.y = __float2bfloat16_rn(y);
    return *reinterpret_cast<unsigned*>(&t);
}

#define MMA_BF16(d, a, b)                                                        \
    asm volatile("mma.sync.aligned.m16n8k16.row.col.f32.bf16.bf16.f32 "          \
                 "{%0,%1,%2,%3},{%4,%5,%6,%7},{%8,%9},{%0,%1,%2,%3};"            \
                 : "+f"(d[0]), "+f"(d[1]), "+f"(d[2]), "+f"(d[3])                 \
                 : "r"(a[0]), "r"(a[1]), "r"(a[2]), "r"(a[3]), "r"(b[0]), "r"(b[1]))

#define LDSM_X4(r, addr)                                                         \
    asm volatile("ldmatrix.sync.aligned.m8n8.x4.shared.b16 {%0,%1,%2,%3}, [%4];" \
                 : "=r"(r[0]), "=r"(r[1]), "=r"(r[2]), "=r"(r[3]) : "r"(addr) : "memory")

#define LDSM_X4_T(r, addr)                                                             \
    asm volatile("ldmatrix.sync.aligned.m8n8.x4.trans.shared.b16 {%0,%1,%2,%3}, [%4];" \
                 : "=r"(r[0]), "=r"(r[1]), "=r"(r[2]), "=r"(r[3]) : "r"(addr) : "memory")

#define AST 20   // A smem row stride in uints (40 bf16 = 80B, LDSM conflict-free)
#define WST 36   // W smem row stride in uints (72 bf16 = 144B, LDSM.T conflict-free)

__global__ void __launch_bounds__(256, 2)
gemm_fused_kernel(const float* __restrict__ A0r, const float* __restrict__ A1r,
                  const float* __restrict__ A2r, const float* __restrict__ A0i,
                  const float* __restrict__ A1i, const float* __restrict__ A2i,
                  const float* __restrict__ W, const float* __restrict__ bias,
                  float* __restrict__ Hr, float* __restrict__ Hi) {
    __shared__ unsigned ash[128 * AST], asl[128 * AST];
    __shared__ unsigned wsh[32 * WST],  wsl[32 * WST];

    int tid = threadIdx.x;
    int lane = tid & 31;
    int warp = tid >> 5;
    int wm = warp >> 2;          // 0..1
    int wn = warp & 3;           // 0..3
    int m0 = blockIdx.y * 128;   // 0..8064
    int n0 = blockIdx.x * 64;
    bool isImag = (m0 >= 4096);
    int mrow0 = m0 & 4095;

    float acc[4][2][4];
    #pragma unroll
    for (int mt = 0; mt < 4; mt++)
        #pragma unroll
        for (int nt = 0; nt < 2; nt++)
            #pragma unroll
            for (int r = 0; r < 4; r++) acc[mt][nt][r] = 0.f;

    unsigned a_hi_base = (unsigned)__cvta_generic_to_shared(ash);
    unsigned a_lo_base = (unsigned)__cvta_generic_to_shared(asl);
    unsigned w_hi_base = (unsigned)__cvta_generic_to_shared(wsh);
    unsigned w_lo_base = (unsigned)__cvta_generic_to_shared(wsl);

    // per-lane LDSM byte offsets (h added later)
    unsigned a_off = ((wm * 64 + (lane & 15)) * (AST * 2) + (lane >> 4) * 8) * 2;
    unsigned w_off = (((((lane >> 3) & 1) * 8 + (lane & 7)) * (WST * 2)) + wn * 16 + (lane >> 4) * 8) * 2;

    for (int ks = 0; ks < 24; ks++) {
        int k0 = ks * 32;
        int plane = k0 >> 8;
        int kc = k0 & 255;
        const float* Ap = isImag ? (plane == 0 ? A0i : (plane == 1 ? A1i : A2i))
                                 : (plane == 0 ? A0r : (plane == 1 ? A1r : A2r));
        // load A tile 128x32
        #pragma unroll
        for (int t = 0; t < 4; t++) {
            int idx = tid + t * 256;
            int r = idx >> 3;
            int c4 = (idx & 7) * 4;
            float4 v = *reinterpret_cast<const float4*>(&Ap[(mrow0 + r) * 256 + kc + c4]);
            float hx = __bfloat162float(__float2bfloat16_rn(v.x));
            float hy = __bfloat162float(__float2bfloat16_rn(v.y));
            float hz = __bfloat162float(__float2bfloat16_rn(v.z));
            float hw = __bfloat162float(__float2bfloat16_rn(v.w));
            int o = r * AST + (c4 >> 1);
            ash[o]     = pack_bf2(v.x, v.y);
            ash[o + 1] = pack_bf2(v.z, v.w);
            asl[o]     = pack_bf2(v.x - hx, v.y - hy);
            asl[o + 1] = pack_bf2(v.z - hz, v.w - hw);
        }
        // load W tile 16x64 -> Ws[k][n]
        #pragma unroll
        for (int t = 0; t < 2; t++) {
            int idx = tid + t * 256;
            int kk = idx >> 4;          // 0..31
            int n4 = (idx & 15) * 4;    // 0..60
            float4 v = *reinterpret_cast<const float4*>(&W[plane * 65536 + (kc + kk) * 256 + n0 + n4]);
            float hx = __bfloat162float(__float2bfloat16_rn(v.x));
            float hy = __bfloat162float(__float2bfloat16_rn(v.y));
            float hz = __bfloat162float(__float2bfloat16_rn(v.z));
            float hw = __bfloat162float(__float2bfloat16_rn(v.w));
            int o = kk * WST + (n4 >> 1);
            wsh[o]     = pack_bf2(v.x, v.y);
            wsh[o + 1] = pack_bf2(v.z, v.w);
            wsl[o]     = pack_bf2(v.x - hx, v.y - hy);
            wsl[o + 1] = pack_bf2(v.z - hz, v.w - hw);
        }
        __syncthreads();

        #pragma unroll
        for (int h = 0; h < 32; h += 16) {
            unsigned ah[4][4], al[4][4];
            #pragma unroll
            for (int mt = 0; mt < 4; mt++) {
                unsigned off = a_off + (mt * 16 * AST * 2 + h) * 2;
                LDSM_X4(ah[mt], a_hi_base + off);
                LDSM_X4(al[mt], a_lo_base + off);
            }
            unsigned bh4[4], bl4[4];
            {
                unsigned off = w_off + (h * WST * 2) * 2;
                LDSM_X4_T(bh4, w_hi_base + off);
                LDSM_X4_T(bl4, w_lo_base + off);
            }
            #pragma unroll
            for (int mt = 0; mt < 4; mt++) {
                #pragma unroll
                for (int nt = 0; nt < 2; nt++) {
                    unsigned bh[2] = {bh4[nt * 2], bh4[nt * 2 + 1]};
                    unsigned bl[2] = {bl4[nt * 2], bl4[nt * 2 + 1]};
                    MMA_BF16(acc[mt][nt], ah[mt], bh);
                    MMA_BF16(acc[mt][nt], ah[mt], bl);
                    MMA_BF16(acc[mt][nt], al[mt], bh);
                }
            }
        }
        __syncthreads();
    }

    // epilogue
    int g = lane >> 2, tig = lane & 3;
    #pragma unroll
    for (int mt = 0; mt < 4; mt++) {
        #pragma unroll
        for (int nt = 0; nt < 2; nt++) {
            int n = n0 + wn * 16 + nt * 8 + tig * 2;
            float b0 = bias[n], b1v = bias[n + 1];
            int ml0 = mrow0 + wm * 64 + mt * 16 + g;
            float* c0 = acc[mt][nt];
            if (!isImag) {
                float2 o0 = make_float2(c0[0] + b0, c0[1] + b1v);
                float2 o1 = make_float2(c0[2] + b0, c0[3] + b1v);
                *reinterpret_cast<float2*>(&Hi[ml0 * 256 + n])       = o0;
                *reinterpret_cast<float2*>(&Hi[(ml0 + 8) * 256 + n]) = o1;
            } else {
                float2 o0 = make_float2(-c0[0] + b0, -c0[1] + b1v);
                float2 o1 = make_float2(-c0[2] + b0, -c0[3] + b1v);
                *reinterpret_cast<float2*>(&Hr[ml0 * 256 + n])       = o0;
                *reinterpret_cast<float2*>(&Hr[(ml0 + 8) * 256 + n]) = o1;
            }
        }
    }
}

// ---------------- classifier + log_softmax ----------------
__global__ void classifier_kernel(const float* __restrict__ Hr, const float* __restrict__ Hi,
                                  const float* __restrict__ Wc, const float* __restrict__ bc,
                                  float* __restrict__ out) {
    int row = blockIdx.x;
    int t = threadIdx.x;   // 128
    __shared__ float x[512];
    __shared__ float lg[40];
    for (int i = t; i < 256; i += 128) {
        x[i]       = Hr[row * 256 + i];
        x[i + 256] = Hi[row * 256 + i];
    }
    __syncthreads();
    int warp = t >> 5, lane = t & 31;
    for (int c = warp; c < 40; c += 4) {
        float s = 0.f;
        #pragma unroll
        for (int k = lane; k < 512; k += 32) s = fmaf(x[k], Wc[c * 512 + k], s);
        #pragma unroll
        for (int o = 16; o > 0; o >>= 1) s += __shfl_xor_sync(0xffffffffu, s, o);
        if (lane == 0) lg[c] = s + bc[c];
    }
    __syncthreads();
    if (warp == 0) {
        float a  = (lane < 40)      ? lg[lane]      : -3.4e38f;
        float b2 = (lane + 32 < 40) ? lg[lane + 32] : -3.4e38f;
        float m = fmaxf(a, b2);
        #pragma unroll
        for (int o = 16; o > 0; o >>= 1) m = fmaxf(m, __shfl_xor_sync(0xffffffffu, m, o));
        float s = ((lane < 40) ? expf(a - m) : 0.f) + ((lane + 32 < 40) ? expf(b2 - m) : 0.f);
        #pragma unroll
        for (int o = 16; o > 0; o >>= 1) s += __shfl_xor_sync(0xffffffffu, s, o);
        float lse = m + logf(s);
        if (lane < 40)      out[row * 40 + lane]      = a - lse;
        if (lane + 32 < 40) out[row * 40 + lane + 32] = b2 - lse;
    }
}

// ---------------- launch ----------------
extern "C" void kernel_launch(void* const* d_in, const int* in_sizes, int n_in,
                              void* d_out, int out_size) {
    const float* real = (const float*)d_in[0];
    const float* imag = (const float*)d_in[1];
    const int*   edges = (const int*)d_in[2];
    const float* qp = (const float*)d_in[3];
    const float* ew = (const float*)d_in[4];
    const float* W1 = (const float*)d_in[5];
    const float* b1 = (const float*)d_in[6];
    const float* W2 = (const float*)d_in[7];
    const float* b2 = (const float*)d_in[8];
    const float* Wc = (const float*)d_in[9];
    const float* bc = (const float*)d_in[10];
    float* out = (float*)d_out;
    int E = in_sizes[4];

    float *Z1r, *Z1i, *Z2r, *Z2i, *H1r, *H1i, *H2r, *H2i;
    cudaGetSymbolAddress((void**)&Z1r, g_Z1r);
    cudaGetSymbolAddress((void**)&Z1i, g_Z1i);
    cudaGetSymbolAddress((void**)&Z2r, g_Z2r);
    cudaGetSymbolAddress((void**)&Z2i, g_Z2i);
    cudaGetSymbolAddress((void**)&H1r, g_H1r);
    cudaGetSymbolAddress((void**)&H1i, g_H1i);
    cudaGetSymbolAddress((void**)&H2r, g_H2r);
    cudaGetSymbolAddress((void**)&H2i, g_H2i);

    // graph build
    zero_kernel<<<TSIZE / 256, 256>>>();
    insert_kernel<<<(E + 255) / 256, 256>>>(edges, ew, E);
    dinv_kernel<<<NN / 256, 256>>>();
    emit_kernel<<<TSIZE / 256, 256>>>(qp);

    // ---- layer 1 ----
    spmm_kernel<<<NN, 256>>>(real, imag, nullptr, nullptr, Z1r, Z1i);
    spmm_kernel<<<NN, 256>>>(Z1r, Z1i, real, imag, Z2r, Z2i);
    gemm_fused_kernel<<<dim3(4, 64), 256>>>(real, Z1r, Z2r, imag, Z1i, Z2i, W1, b1, H1r, H1i);

    // ---- layer 2 ----
    spmm_kernel<<<NN, 256>>>(H1r, H1i, nullptr, nullptr, Z1r, Z1i);
    spmm_kernel<<<NN, 256>>>(Z1r, Z1i, H1r, H1i, Z2r, Z2i);
    gemm_fused_kernel<<<dim3(4, 64), 256>>>(H1r, Z1r, Z2r, H1i, Z1i, Z2i, W2, b2, H2r, H2i);

    classifier_kernel<<<NN, 128>>>(H2r, H2i, Wc, bc, out);
}

// round 12
// speedup vs baseline: 1.2086x; 1.0012x over previous
#include <cuda_runtime.h>
#include <cuda_bf16.h>
#include <math.h>

#define NN   4096
#define FF   256
#define ELLW 256
#define TBITS 19
#define TSIZE (1 << TBITS)
#define TMASK (TSIZE - 1)

// ---------------- scratch (device globals) ----------------
__device__ int   g_hkey[TSIZE];
__device__ float g_hvalF[TSIZE];     // weight of direction min->max (and self loops)
__device__ float g_hvalR[TSIZE];     // weight of direction max->min
__device__ float g_deg[NN];
__device__ float g_dinv[NN];
__device__ int   g_cnt[NN];
__device__ int4  g_ell[NN * ELLW];   // AoS: {col, lre_bits, lim_bits, pad}
__device__ float g_Z1r[NN * FF], g_Z1i[NN * FF];
__device__ float g_Z2r[NN * FF], g_Z2i[NN * FF];
__device__ float g_H1r[NN * FF], g_H1i[NN * FF];
__device__ float g_H2r[NN * FF], g_H2i[NN * FF];

__device__ __forceinline__ unsigned hash_key(int key) {
    return ((unsigned)key * 2654435761u) >> (32 - TBITS);
}

// ---------------- graph build ----------------
__global__ void zero_kernel() {
    int idx = blockIdx.x * blockDim.x + threadIdx.x;
    if (idx < TSIZE) { g_hkey[idx] = -1; g_hvalF[idx] = 0.f; g_hvalR[idx] = 0.f; }
    if (idx < NN)    { g_deg[idx] = 0.f; g_cnt[idx] = 0; }
}

__global__ void insert_kernel(const int* __restrict__ edges,
                              const float* __restrict__ w, int E) {
    int e = blockIdx.x * blockDim.x + threadIdx.x;
    if (e >= E) return;
    int r = edges[e];
    int c = edges[E + e];
    float we = w[e];
    atomicAdd(&g_deg[r], 0.5f * we);
    atomicAdd(&g_deg[c], 0.5f * we);
    int lo = min(r, c), hi = max(r, c);
    int key = (lo << 12) | hi;
    unsigned h = hash_key(key) & TMASK;
    while (true) {
        int prev = atomicCAS(&g_hkey[h], -1, key);
        if (prev == -1 || prev == key) {
            if (r <= c) atomicAdd(&g_hvalF[h], we);
            else        atomicAdd(&g_hvalR[h], we);
            break;
        }
        h = (h + 1) & TMASK;
    }
}

__global__ void dinv_kernel() {
    int i = blockIdx.x * blockDim.x + threadIdx.x;
    if (i < NN) {
        float d = g_deg[i];
        if (d == 0.f) d = 1.f;
        g_dinv[i] = rsqrtf(d);
    }
}

__device__ __forceinline__ void ell_push(int r, int c, float lre, float lim) {
    int slot = atomicAdd(&g_cnt[r], 1);
    if (slot < ELLW) {
        g_ell[r * ELLW + slot] =
            make_int4(c, __float_as_int(lre), __float_as_int(lim), 0);
    }
}

__global__ void emit_kernel(const float* __restrict__ qp) {
    int s = blockIdx.x * blockDim.x + threadIdx.x;
    if (s >= TSIZE) return;
    int key = g_hkey[s];
    if (key < 0) return;
    int i = key >> 12;         // i <= j
    int j = key & 4095;
    float F = g_hvalF[s];      // A[i][j]
    float R = g_hvalR[s];      // A[j][i]
    float q = __ldg(qp);
    if (i == j) {
        float di = g_dinv[i];
        ell_push(i, i, -di * di * F, 0.f);
        return;
    }
    float asym = 0.5f * (F + R);
    float an = g_dinv[i] * asym * g_dinv[j];
    float th = 6.283185307179586f * q * (F - R);
    float sn, cs;
    __sincosf(th, &sn, &cs);
    // conj(L)[i][j] = -A_n * exp(-i*th)
    ell_push(i, j, -an * cs,  an * sn);
    ell_push(j, i, -an * cs, -an * sn);
}

// ---------------- complex SpMM (ELL, AoS) ----------------
__global__ void spmm_kernel(const float* __restrict__ Xr, const float* __restrict__ Xi,
                            const float* __restrict__ Sr, const float* __restrict__ Si,
                            float* __restrict__ Yr, float* __restrict__ Yi) {
    int row = blockIdx.x;
    int t = threadIdx.x;
    int cnt = g_cnt[row];
    if (cnt > ELLW) cnt = ELLW;
    __shared__ int   sc[ELLW];
    __shared__ float slr[ELLW];
    __shared__ float sli[ELLW];
    for (int k = t; k < cnt; k += 256) {
        int4 v = g_ell[row * ELLW + k];
        sc [k] = v.x;
        slr[k] = __int_as_float(v.y);
        sli[k] = __int_as_float(v.z);
    }
    __syncthreads();
    float ar = 0.f, ai = 0.f;
    #pragma unroll 4
    for (int k = 0; k < cnt; k++) {
        int   c  = sc[k];
        float lr = slr[k];
        float li = sli[k];
        float xr = __ldg(&Xr[c * FF + t]);
        float xi = __ldg(&Xi[c * FF + t]);
        ar = fmaf(lr, xr, ar);
        ar = fmaf(-li, xi, ar);
        ai = fmaf(lr, xi, ai);
        ai = fmaf(li, xr, ai);
    }
    int o = row * FF + t;
    if (Sr) {
        Yr[o] = 2.f * ar - Sr[o];
        Yi[o] = 2.f * ai - Si[o];
    } else {
        Yr[o] = ar;
        Yi[o] = ai;
    }
}

// ---------------- fused tensor-core GEMM (bf16 3-term split) ----------------
// C[8192,256] = [Zr;Zi](8192x768) @ Wcat(768x256); rows<4096 -> Hi=C+b, rows>=4096 -> Hr=-C+b
// BM=128, BN=64, BK=32; 256 thr = 8 warps (2m x 4n); warp tile 64x16.

__device__ __forceinline__ unsigned pack_bf2(float x, float y) {
    __nv_bfloat162 t;
    t.x = __float2bfloat16_rn(x);
    t.y = __float2bfloat16_rn(y);
    return *reinterpret_cast<unsigned*>(&t);
}

#define MMA_BF16(d, a, b)                                                        \
    asm volatile("mma.sync.aligned.m16n8k16.row.col.f32.bf16.bf16.f32 "          \
                 "{%0,%1,%2,%3},{%4,%5,%6,%7},{%8,%9},{%0,%1,%2,%3};"            \
                 : "+f"(d[0]), "+f"(d[1]), "+f"(d[2]), "+f"(d[3])                 \
                 : "r"(a[0]), "r"(a[1]), "r"(a[2]), "r"(a[3]), "r"(b[0]), "r"(b[1]))

#define LDSM_X4(r, addr)                                                         \
    asm volatile("ldmatrix.sync.aligned.m8n8.x4.shared.b16 {%0,%1,%2,%3}, [%4];" \
                 : "=r"(r[0]), "=r"(r[1]), "=r"(r[2]), "=r"(r[3]) : "r"(addr) : "memory")

#define LDSM_X4_T(r, addr)                                                             \
    asm volatile("ldmatrix.sync.aligned.m8n8.x4.trans.shared.b16 {%0,%1,%2,%3}, [%4];" \
                 : "=r"(r[0]), "=r"(r[1]), "=r"(r[2]), "=r"(r[3]) : "r"(addr) : "memory")

#define AST 20   // A smem row stride in uints (40 bf16 = 80B, LDSM conflict-free)
#define WST 36   // W smem row stride in uints (72 bf16 = 144B, LDSM.T conflict-free)

__global__ void __launch_bounds__(256, 2)
gemm_fused_kernel(const float* __restrict__ A0r, const float* __restrict__ A1r,
                  const float* __restrict__ A2r, const float* __restrict__ A0i,
                  const float* __restrict__ A1i, const float* __restrict__ A2i,
                  const float* __restrict__ W, const float* __restrict__ bias,
                  float* __restrict__ Hr, float* __restrict__ Hi) {
    __shared__ unsigned ash[128 * AST], asl[128 * AST];
    __shared__ unsigned wsh[32 * WST],  wsl[32 * WST];

    int tid = threadIdx.x;
    int lane = tid & 31;
    int warp = tid >> 5;
    int wm = warp >> 2;          // 0..1
    int wn = warp & 3;           // 0..3
    int m0 = blockIdx.y * 128;   // 0..8064
    int n0 = blockIdx.x * 64;
    bool isImag = (m0 >= 4096);
    int mrow0 = m0 & 4095;

    float acc[4][2][4];
    #pragma unroll
    for (int mt = 0; mt < 4; mt++)
        #pragma unroll
        for (int nt = 0; nt < 2; nt++)
            #pragma unroll
            for (int r = 0; r < 4; r++) acc[mt][nt][r] = 0.f;

    unsigned a_hi_base = (unsigned)__cvta_generic_to_shared(ash);
    unsigned a_lo_base = (unsigned)__cvta_generic_to_shared(asl);
    unsigned w_hi_base = (unsigned)__cvta_generic_to_shared(wsh);
    unsigned w_lo_base = (unsigned)__cvta_generic_to_shared(wsl);

    // per-lane LDSM byte offsets (h added later)
    unsigned a_off = ((wm * 64 + (lane & 15)) * (AST * 2) + (lane >> 4) * 8) * 2;
    unsigned w_off = (((((lane >> 3) & 1) * 8 + (lane & 7)) * (WST * 2)) + wn * 16 + (lane >> 4) * 8) * 2;

    for (int ks = 0; ks < 24; ks++) {
        int k0 = ks * 32;
        int plane = k0 >> 8;
        int kc = k0 & 255;
        const float* Ap = isImag ? (plane == 0 ? A0i : (plane == 1 ? A1i : A2i))
                                 : (plane == 0 ? A0r : (plane == 1 ? A1r : A2r));
        // load A tile 128x32
        #pragma unroll
        for (int t = 0; t < 4; t++) {
            int idx = tid + t * 256;
            int r = idx >> 3;
            int c4 = (idx & 7) * 4;
            float4 v = *reinterpret_cast<const float4*>(&Ap[(mrow0 + r) * 256 + kc + c4]);
            float hx = __bfloat162float(__float2bfloat16_rn(v.x));
            float hy = __bfloat162float(__float2bfloat16_rn(v.y));
            float hz = __bfloat162float(__float2bfloat16_rn(v.z));
            float hw = __bfloat162float(__float2bfloat16_rn(v.w));
            int o = r * AST + (c4 >> 1);
            ash[o]     = pack_bf2(v.x, v.y);
            ash[o + 1] = pack_bf2(v.z, v.w);
            asl[o]     = pack_bf2(v.x - hx, v.y - hy);
            asl[o + 1] = pack_bf2(v.z - hz, v.w - hw);
        }
        // load W tile 32x64 (k-major): 2 iters x 256 thr x float4 = 2048 elems
        #pragma unroll
        for (int t = 0; t < 2; t++) {
            int idx = tid + t * 256;
            int kk = idx >> 4;          // 0..31
            int n4 = (idx & 15) * 4;    // 0..60
            float4 v = *reinterpret_cast<const float4*>(&W[plane * 65536 + (kc + kk) * 256 + n0 + n4]);
            float hx = __bfloat162float(__float2bfloat16_rn(v.x));
            float hy = __bfloat162float(__float2bfloat16_rn(v.y));
            float hz = __bfloat162float(__float2bfloat16_rn(v.z));
            float hw = __bfloat162float(__float2bfloat16_rn(v.w));
            int o = kk * WST + (n4 >> 1);
            wsh[o]     = pack_bf2(v.x, v.y);
            wsh[o + 1] = pack_bf2(v.z, v.w);
            wsl[o]     = pack_bf2(v.x - hx, v.y - hy);
            wsl[o + 1] = pack_bf2(v.z - hz, v.w - hw);
        }
        __syncthreads();

        #pragma unroll
        for (int h = 0; h < 32; h += 16) {
            unsigned ah[4][4], al[4][4];
            #pragma unroll
            for (int mt = 0; mt < 4; mt++) {
                unsigned off = a_off + (mt * 16 * AST * 2 + h) * 2;
                LDSM_X4(ah[mt], a_hi_base + off);
                LDSM_X4(al[mt], a_lo_base + off);
            }
            unsigned bh4[4], bl4[4];
            {
                unsigned off = w_off + (h * WST * 2) * 2;
                LDSM_X4_T(bh4, w_hi_base + off);
                LDSM_X4_T(bl4, w_lo_base + off);
            }
            #pragma unroll
            for (int mt = 0; mt < 4; mt++) {
                #pragma unroll
                for (int nt = 0; nt < 2; nt++) {
                    unsigned bh[2] = {bh4[nt * 2], bh4[nt * 2 + 1]};
                    unsigned bl[2] = {bl4[nt * 2], bl4[nt * 2 + 1]};
                    MMA_BF16(acc[mt][nt], ah[mt], bh);
                    MMA_BF16(acc[mt][nt], ah[mt], bl);
                    MMA_BF16(acc[mt][nt], al[mt], bh);
                }
            }
        }
        __syncthreads();
    }

    // epilogue
    int g = lane >> 2, tig = lane & 3;
    #pragma unroll
    for (int mt = 0; mt < 4; mt++) {
        #pragma unroll
        for (int nt = 0; nt < 2; nt++) {
            int n = n0 + wn * 16 + nt * 8 + tig * 2;
            float b0 = bias[n], b1v = bias[n + 1];
            int ml0 = mrow0 + wm * 64 + mt * 16 + g;
            float* c0 = acc[mt][nt];
            if (!isImag) {
                float2 o0 = make_float2(c0[0] + b0, c0[1] + b1v);
                float2 o1 = make_float2(c0[2] + b0, c0[3] + b1v);
                *reinterpret_cast<float2*>(&Hi[ml0 * 256 + n])       = o0;
                *reinterpret_cast<float2*>(&Hi[(ml0 + 8) * 256 + n]) = o1;
            } else {
                float2 o0 = make_float2(-c0[0] + b0, -c0[1] + b1v);
                float2 o1 = make_float2(-c0[2] + b0, -c0[3] + b1v);
                *reinterpret_cast<float2*>(&Hr[ml0 * 256 + n])       = o0;
                *reinterpret_cast<float2*>(&Hr[(ml0 + 8) * 256 + n]) = o1;
            }
        }
    }
}

// ---------------- classifier + log_softmax ----------------
__global__ void classifier_kernel(const float* __restrict__ Hr, const float* __restrict__ Hi,
                                  const float* __restrict__ Wc, const float* __restrict__ bc,
                                  float* __restrict__ out) {
    int row = blockIdx.x;
    int t = threadIdx.x;   // 128
    __shared__ float x[512];
    __shared__ float lg[40];
    for (int i = t; i < 256; i += 128) {
        x[i]       = Hr[row * 256 + i];
        x[i + 256] = Hi[row * 256 + i];
    }
    __syncthreads();
    int warp = t >> 5, lane = t & 31;
    for (int c = warp; c < 40; c += 4) {
        float s = 0.f;
        #pragma unroll
        for (int k = lane; k < 512; k += 32) s = fmaf(x[k], Wc[c * 512 + k], s);
        #pragma unroll
        for (int o = 16; o > 0; o >>= 1) s += __shfl_xor_sync(0xffffffffu, s, o);
        if (lane == 0) lg[c] = s + bc[c];
    }
    __syncthreads();
    if (warp == 0) {
        float a  = (lane < 40)      ? lg[lane]      : -3.4e38f;
        float b2 = (lane + 32 < 40) ? lg[lane + 32] : -3.4e38f;
        float m = fmaxf(a, b2);
        #pragma unroll
        for (int o = 16; o > 0; o >>= 1) m = fmaxf(m, __shfl_xor_sync(0xffffffffu, m, o));
        float s = ((lane < 40) ? expf(a - m) : 0.f) + ((lane + 32 < 40) ? expf(b2 - m) : 0.f);
        #pragma unroll
        for (int o = 16; o > 0; o >>= 1) s += __shfl_xor_sync(0xffffffffu, s, o);
        float lse = m + logf(s);
        if (lane < 40)      out[row * 40 + lane]      = a - lse;
        if (lane + 32 < 40) out[row * 40 + lane + 32] = b2 - lse;
    }
}

// ---------------- launch ----------------
extern "C" void kernel_launch(void* const* d_in, const int* in_sizes, int n_in,
                              void* d_out, int out_size) {
    const float* real = (const float*)d_in[0];
    const float* imag = (const float*)d_in[1];
    const int*   edges = (const int*)d_in[2];
    const float* qp = (const float*)d_in[3];
    const float* ew = (const float*)d_in[4];
    const float* W1 = (const float*)d_in[5];
    const float* b1 = (const float*)d_in[6];
    const float* W2 = (const float*)d_in[7];
    const float* b2 = (const float*)d_in[8];
    const float* Wc = (const float*)d_in[9];
    const float* bc = (const float*)d_in[10];
    float* out = (float*)d_out;
    int E = in_sizes[4];

    float *Z1r, *Z1i, *Z2r, *Z2i, *H1r, *H1i, *H2r, *H2i;
    cudaGetSymbolAddress((void**)&Z1r, g_Z1r);
    cudaGetSymbolAddress((void**)&Z1i, g_Z1i);
    cudaGetSymbolAddress((void**)&Z2r, g_Z2r);
    cudaGetSymbolAddress((void**)&Z2i, g_Z2i);
    cudaGetSymbolAddress((void**)&H1r, g_H1r);
    cudaGetSymbolAddress((void**)&H1i, g_H1i);
    cudaGetSymbolAddress((void**)&H2r, g_H2r);
    cudaGetSymbolAddress((void**)&H2i, g_H2i);

    // graph build
    zero_kernel<<<TSIZE / 256, 256>>>();
    insert_kernel<<<(E + 255) / 256, 256>>>(edges, ew, E);
    dinv_kernel<<<NN / 256, 256>>>();
    emit_kernel<<<TSIZE / 256, 256>>>(qp);

    // ---- layer 1 ----
    spmm_kernel<<<NN, 256>>>(real, imag, nullptr, nullptr, Z1r, Z1i);
    spmm_kernel<<<NN, 256>>>(Z1r, Z1i, real, imag, Z2r, Z2i);
    gemm_fused_kernel<<<dim3(4, 64), 256>>>(real, Z1r, Z2r, imag, Z1i, Z2i, W1, b1, H1r, H1i);

    // ---- layer 2 ----
    spmm_kernel<<<NN, 256>>>(H1r, H1i, nullptr, nullptr, Z1r, Z1i);
    spmm_kernel<<<NN, 256>>>(Z1r, Z1i, H1r, H1i, Z2r, Z2i);
    gemm_fused_kernel<<<dim3(4, 64), 256>>>(H1r, Z1r, Z2r, H1i, Z1i, Z2i, W2, b2, H2r, H2i);

    classifier_kernel<<<NN, 128>>>(H2r, H2i, Wc, bc, out);
}

// round 13
// speedup vs baseline: 1.3363x; 1.1056x over previous
#include <cuda_runtime.h>
#include <cuda_bf16.h>
#include <math.h>

#define NN   4096
#define FF   256
#define ELLW 256
#define TBITS 19
#define TSIZE (1 << TBITS)
#define TMASK (TSIZE - 1)

// ---------------- scratch (device globals) ----------------
__device__ int   g_hkey[TSIZE];
__device__ float g_hvalF[TSIZE];
__device__ float g_hvalR[TSIZE];
__device__ float g_deg[NN];
__device__ float g_dinv[NN];
__device__ int   g_cnt[NN];
__device__ int4  g_ell[NN * ELLW];   // AoS: {col, lre_bits, lim_bits, pad}
__device__ float g_Z1r[NN * FF], g_Z1i[NN * FF];
__device__ float g_Z2r[NN * FF], g_Z2i[NN * FF];
__device__ float g_H1r[NN * FF], g_H1i[NN * FF];
// layer-2 folded-classifier scratch
__device__ float g_C[7][256 * 64];     // combination matrices [256 x 64]
__device__ float g_cvec[64];           // b2 * (Wcr+Wci)^T
__device__ float g_Dp[4][NN * 64];     // partial logits planes
__device__ float g_Vp[4][NN * 64];     // V plane partials
__device__ float g_Vre[NN * 64], g_Vim[NN * 64];
__device__ float g_T[NN * 64];         // Re[L V]

__device__ __forceinline__ unsigned hash_key(int key) {
    return ((unsigned)key * 2654435761u) >> (32 - TBITS);
}

// ---------------- graph build (R12-proven) ----------------
__global__ void zero_kernel() {
    int idx = blockIdx.x * blockDim.x + threadIdx.x;
    if (idx < TSIZE) { g_hkey[idx] = -1; g_hvalF[idx] = 0.f; g_hvalR[idx] = 0.f; }
    if (idx < NN)    { g_deg[idx] = 0.f; g_cnt[idx] = 0; }
}

__global__ void insert_kernel(const int* __restrict__ edges,
                              const float* __restrict__ w, int E) {
    int e = blockIdx.x * blockDim.x + threadIdx.x;
    if (e >= E) return;
    int r = edges[e];
    int c = edges[E + e];
    float we = w[e];
    atomicAdd(&g_deg[r], 0.5f * we);
    atomicAdd(&g_deg[c], 0.5f * we);
    int lo = min(r, c), hi = max(r, c);
    int key = (lo << 12) | hi;
    unsigned h = hash_key(key) & TMASK;
    while (true) {
        int prev = atomicCAS(&g_hkey[h], -1, key);
        if (prev == -1 || prev == key) {
            if (r <= c) atomicAdd(&g_hvalF[h], we);
            else        atomicAdd(&g_hvalR[h], we);
            break;
        }
        h = (h + 1) & TMASK;
    }
}

__global__ void dinv_kernel() {
    int i = blockIdx.x * blockDim.x + threadIdx.x;
    if (i < NN) {
        float d = g_deg[i];
        if (d == 0.f) d = 1.f;
        g_dinv[i] = rsqrtf(d);
    }
}

__device__ __forceinline__ void ell_push(int r, int c, float lre, float lim) {
    int slot = atomicAdd(&g_cnt[r], 1);
    if (slot < ELLW) {
        g_ell[r * ELLW + slot] =
            make_int4(c, __float_as_int(lre), __float_as_int(lim), 0);
    }
}

__global__ void emit_kernel(const float* __restrict__ qp) {
    int s = blockIdx.x * blockDim.x + threadIdx.x;
    if (s >= TSIZE) return;
    int key = g_hkey[s];
    if (key < 0) return;
    int i = key >> 12;         // i <= j
    int j = key & 4095;
    float F = g_hvalF[s];
    float R = g_hvalR[s];
    float q = __ldg(qp);
    if (i == j) {
        float di = g_dinv[i];
        ell_push(i, i, -di * di * F, 0.f);
        return;
    }
    float asym = 0.5f * (F + R);
    float an = g_dinv[i] * asym * g_dinv[j];
    float th = 6.283185307179586f * q * (F - R);
    float sn, cs;
    __sincosf(th, &sn, &cs);
    ell_push(i, j, -an * cs,  an * sn);
    ell_push(j, i, -an * cs, -an * sn);
}

// ---------------- complex SpMM (ELL, AoS), full width ----------------
__global__ void spmm_kernel(const float* __restrict__ Xr, const float* __restrict__ Xi,
                            const float* __restrict__ Sr, const float* __restrict__ Si,
                            float* __restrict__ Yr, float* __restrict__ Yi) {
    int row = blockIdx.x;
    int t = threadIdx.x;
    int cnt = g_cnt[row];
    if (cnt > ELLW) cnt = ELLW;
    __shared__ int   sc[ELLW];
    __shared__ float slr[ELLW];
    __shared__ float sli[ELLW];
    for (int k = t; k < cnt; k += 256) {
        int4 v = g_ell[row * ELLW + k];
        sc [k] = v.x;
        slr[k] = __int_as_float(v.y);
        sli[k] = __int_as_float(v.z);
    }
    __syncthreads();
    float ar = 0.f, ai = 0.f;
    #pragma unroll 4
    for (int k = 0; k < cnt; k++) {
        int   c  = sc[k];
        float lr = slr[k];
        float li = sli[k];
        float xr = __ldg(&Xr[c * FF + t]);
        float xi = __ldg(&Xi[c * FF + t]);
        ar = fmaf(lr, xr, ar);
        ar = fmaf(-li, xi, ar);
        ai = fmaf(lr, xi, ai);
        ai = fmaf(li, xr, ai);
    }
    int o = row * FF + t;
    if (Sr) {
        Yr[o] = 2.f * ar - Sr[o];
        Yi[o] = 2.f * ai - Si[o];
    } else {
        Yr[o] = ar;
        Yi[o] = ai;
    }
}

// ---------------- 64-wide spmm: T = Re[L V] ----------------
__global__ void spmm64_kernel(const float* __restrict__ Vre, const float* __restrict__ Vim,
                              float* __restrict__ T) {
    int row = blockIdx.x;
    int t = threadIdx.x;   // 64
    int cnt = g_cnt[row];
    if (cnt > ELLW) cnt = ELLW;
    __shared__ int   sc[ELLW];
    __shared__ float slr[ELLW];
    __shared__ float sli[ELLW];
    for (int k = t; k < cnt; k += 64) {
        int4 v = g_ell[row * ELLW + k];
        sc [k] = v.x;
        slr[k] = __int_as_float(v.y);
        sli[k] = __int_as_float(v.z);
    }
    __syncthreads();
    float acc = 0.f;
    #pragma unroll 4
    for (int k = 0; k < cnt; k++) {
        int c = sc[k];
        acc = fmaf(slr[k],  __ldg(&Vre[c * 64 + t]), acc);
        acc = fmaf(-sli[k], __ldg(&Vim[c * 64 + t]), acc);
    }
    T[row * 64 + t] = acc;
}

// ---------------- GEMM machinery (proven) ----------------
__device__ __forceinline__ unsigned pack_bf2(float x, float y) {
    __nv_bfloat162 t;
    t.x = __float2bfloat16_rn(x);
    t.y = __float2bfloat16_rn(y);
    return *reinterpret_cast<unsigned*>(&t);
}

#define MMA_BF16(d, a, b)                                                        \
    asm volatile("mma.sync.aligned.m16n8k16.row.col.f32.bf16.bf16.f32 "          \
                 "{%0,%1,%2,%3},{%4,%5,%6,%7},{%8,%9},{%0,%1,%2,%3};"            \
                 : "+f"(d[0]), "+f"(d[1]), "+f"(d[2]), "+f"(d[3])                 \
                 : "r"(a[0]), "r"(a[1]), "r"(a[2]), "r"(a[3]), "r"(b[0]), "r"(b[1]))

#define LDSM_X4(r, addr)                                                         \
    asm volatile("ldmatrix.sync.aligned.m8n8.x4.shared.b16 {%0,%1,%2,%3}, [%4];" \
                 : "=r"(r[0]), "=r"(r[1]), "=r"(r[2]), "=r"(r[3]) : "r"(addr) : "memory")

#define LDSM_X4_T(r, addr)                                                             \
    asm volatile("ldmatrix.sync.aligned.m8n8.x4.trans.shared.b16 {%0,%1,%2,%3}, [%4];" \
                 : "=r"(r[0]), "=r"(r[1]), "=r"(r[2]), "=r"(r[3]) : "r"(addr) : "memory")

#define AST 20   // A smem row stride in uints (80B, LDSM conflict-free)
#define WST 36   // W smem row stride in uints (144B, LDSM.T conflict-free)

// ---------- layer-1 fused GEMM (R12-proven, verbatim) ----------
__global__ void __launch_bounds__(256, 2)
gemm_fused_kernel(const float* __restrict__ A0r, const float* __restrict__ A1r,
                  const float* __restrict__ A2r, const float* __restrict__ A0i,
                  const float* __restrict__ A1i, const float* __restrict__ A2i,
                  const float* __restrict__ W, const float* __restrict__ bias,
                  float* __restrict__ Hr, float* __restrict__ Hi) {
    __shared__ unsigned ash[128 * AST], asl[128 * AST];
    __shared__ unsigned wsh[32 * WST],  wsl[32 * WST];

    int tid = threadIdx.x;
    int lane = tid & 31;
    int warp = tid >> 5;
    int wm = warp >> 2;
    int wn = warp & 3;
    int m0 = blockIdx.y * 128;
    int n0 = blockIdx.x * 64;
    bool isImag = (m0 >= 4096);
    int mrow0 = m0 & 4095;

    float acc[4][2][4];
    #pragma unroll
    for (int mt = 0; mt < 4; mt++)
        #pragma unroll
        for (int nt = 0; nt < 2; nt++)
            #pragma unroll
            for (int r = 0; r < 4; r++) acc[mt][nt][r] = 0.f;

    unsigned a_hi_base = (unsigned)__cvta_generic_to_shared(ash);
    unsigned a_lo_base = (unsigned)__cvta_generic_to_shared(asl);
    unsigned w_hi_base = (unsigned)__cvta_generic_to_shared(wsh);
    unsigned w_lo_base = (unsigned)__cvta_generic_to_shared(wsl);

    unsigned a_off = ((wm * 64 + (lane & 15)) * (AST * 2) + (lane >> 4) * 8) * 2;
    unsigned w_off = (((((lane >> 3) & 1) * 8 + (lane & 7)) * (WST * 2)) + wn * 16 + (lane >> 4) * 8) * 2;

    for (int ks = 0; ks < 24; ks++) {
        int k0 = ks * 32;
        int plane = k0 >> 8;
        int kc = k0 & 255;
        const float* Ap = isImag ? (plane == 0 ? A0i : (plane == 1 ? A1i : A2i))
                                 : (plane == 0 ? A0r : (plane == 1 ? A1r : A2r));
        #pragma unroll
        for (int t = 0; t < 4; t++) {
            int idx = tid + t * 256;
            int r = idx >> 3;
            int c4 = (idx & 7) * 4;
            float4 v = *reinterpret_cast<const float4*>(&Ap[(mrow0 + r) * 256 + kc + c4]);
            float hx = __bfloat162float(__float2bfloat16_rn(v.x));
            float hy = __bfloat162float(__float2bfloat16_rn(v.y));
            float hz = __bfloat162float(__float2bfloat16_rn(v.z));
            float hw = __bfloat162float(__float2bfloat16_rn(v.w));
            int o = r * AST + (c4 >> 1);
            ash[o]     = pack_bf2(v.x, v.y);
            ash[o + 1] = pack_bf2(v.z, v.w);
            asl[o]     = pack_bf2(v.x - hx, v.y - hy);
            asl[o + 1] = pack_bf2(v.z - hz, v.w - hw);
        }
        #pragma unroll
        for (int t = 0; t < 2; t++) {
            int idx = tid + t * 256;
            int kk = idx >> 4;
            int n4 = (idx & 15) * 4;
            float4 v = *reinterpret_cast<const float4*>(&W[plane * 65536 + (kc + kk) * 256 + n0 + n4]);
            float hx = __bfloat162float(__float2bfloat16_rn(v.x));
            float hy = __bfloat162float(__float2bfloat16_rn(v.y));
            float hz = __bfloat162float(__float2bfloat16_rn(v.z));
            float hw = __bfloat162float(__float2bfloat16_rn(v.w));
            int o = kk * WST + (n4 >> 1);
            wsh[o]     = pack_bf2(v.x, v.y);
            wsh[o + 1] = pack_bf2(v.z, v.w);
            wsl[o]     = pack_bf2(v.x - hx, v.y - hy);
            wsl[o + 1] = pack_bf2(v.z - hz, v.w - hw);
        }
        __syncthreads();

        #pragma unroll
        for (int h = 0; h < 32; h += 16) {
            unsigned ah[4][4], al[4][4];
            #pragma unroll
            for (int mt = 0; mt < 4; mt++) {
                unsigned off = a_off + (mt * 16 * AST * 2 + h) * 2;
                LDSM_X4(ah[mt], a_hi_base + off);
                LDSM_X4(al[mt], a_lo_base + off);
            }
            unsigned bh4[4], bl4[4];
            {
                unsigned off = w_off + (h * WST * 2) * 2;
                LDSM_X4_T(bh4, w_hi_base + off);
                LDSM_X4_T(bl4, w_lo_base + off);
            }
            #pragma unroll
            for (int mt = 0; mt < 4; mt++) {
                #pragma unroll
                for (int nt = 0; nt < 2; nt++) {
                    unsigned bh[2] = {bh4[nt * 2], bh4[nt * 2 + 1]};
                    unsigned bl[2] = {bl4[nt * 2], bl4[nt * 2 + 1]};
                    MMA_BF16(acc[mt][nt], ah[mt], bh);
                    MMA_BF16(acc[mt][nt], ah[mt], bl);
                    MMA_BF16(acc[mt][nt], al[mt], bh);
                }
            }
        }
        __syncthreads();
    }

    int g = lane >> 2, tig = lane & 3;
    #pragma unroll
    for (int mt = 0; mt < 4; mt++) {
        #pragma unroll
        for (int nt = 0; nt < 2; nt++) {
            int n = n0 + wn * 16 + nt * 8 + tig * 2;
            float b0 = bias[n], b1v = bias[n + 1];
            int ml0 = mrow0 + wm * 64 + mt * 16 + g;
            float* c0 = acc[mt][nt];
            if (!isImag) {
                float2 o0 = make_float2(c0[0] + b0, c0[1] + b1v);
                float2 o1 = make_float2(c0[2] + b0, c0[3] + b1v);
                *reinterpret_cast<float2*>(&Hi[ml0 * 256 + n])       = o0;
                *reinterpret_cast<float2*>(&Hi[(ml0 + 8) * 256 + n]) = o1;
            } else {
                float2 o0 = make_float2(-c0[0] + b0, -c0[1] + b1v);
                float2 o1 = make_float2(-c0[2] + b0, -c0[3] + b1v);
                *reinterpret_cast<float2*>(&Hr[ml0 * 256 + n])       = o0;
                *reinterpret_cast<float2*>(&Hr[(ml0 + 8) * 256 + n]) = o1;
            }
        }
    }
}

// ---------- plane products: O[p] = A[p] @ C[p]  (K=256, N=64, raw fp32) ----------
struct PPArgs {
    const float* A[8];
    const float* C[8];
    float* O[8];
};

__global__ void __launch_bounds__(256, 2)
planeprod_kernel(PPArgs pp) {
    __shared__ unsigned ash[128 * AST], asl[128 * AST];
    __shared__ unsigned wsh[32 * WST],  wsl[32 * WST];

    int tid = threadIdx.x;
    int lane = tid & 31;
    int warp = tid >> 5;
    int wm = warp >> 2;
    int wn = warp & 3;
    int p = blockIdx.x;
    int m0 = blockIdx.y * 128;
    const float* Ap = pp.A[p];
    const float* Cm = pp.C[p];
    float* Op = pp.O[p];

    float acc[4][2][4];
    #pragma unroll
    for (int mt = 0; mt < 4; mt++)
        #pragma unroll
        for (int nt = 0; nt < 2; nt++)
            #pragma unroll
            for (int r = 0; r < 4; r++) acc[mt][nt][r] = 0.f;

    unsigned a_hi_base = (unsigned)__cvta_generic_to_shared(ash);
    unsigned a_lo_base = (unsigned)__cvta_generic_to_shared(asl);
    unsigned w_hi_base = (unsigned)__cvta_generic_to_shared(wsh);
    unsigned w_lo_base = (unsigned)__cvta_generic_to_shared(wsl);

    unsigned a_off = ((wm * 64 + (lane & 15)) * (AST * 2) + (lane >> 4) * 8) * 2;
    unsigned w_off = (((((lane >> 3) & 1) * 8 + (lane & 7)) * (WST * 2)) + wn * 16 + (lane >> 4) * 8) * 2;

    for (int ks = 0; ks < 8; ks++) {
        int kc = ks * 32;
        // A tile 128x32
        #pragma unroll
        for (int t = 0; t < 4; t++) {
            int idx = tid + t * 256;
            int r = idx >> 3;
            int c4 = (idx & 7) * 4;
            float4 v = *reinterpret_cast<const float4*>(&Ap[(m0 + r) * 256 + kc + c4]);
            float hx = __bfloat162float(__float2bfloat16_rn(v.x));
            float hy = __bfloat162float(__float2bfloat16_rn(v.y));
            float hz = __bfloat162float(__float2bfloat16_rn(v.z));
            float hw = __bfloat162float(__float2bfloat16_rn(v.w));
            int o = r * AST + (c4 >> 1);
            ash[o]     = pack_bf2(v.x, v.y);
            ash[o + 1] = pack_bf2(v.z, v.w);
            asl[o]     = pack_bf2(v.x - hx, v.y - hy);
            asl[o + 1] = pack_bf2(v.z - hz, v.w - hw);
        }
        // C tile 32x64 (pitch 64)
        #pragma unroll
        for (int t = 0; t < 2; t++) {
            int idx = tid + t * 256;
            int kk = idx >> 4;
            int n4 = (idx & 15) * 4;
            float4 v = *reinterpret_cast<const float4*>(&Cm[(kc + kk) * 64 + n4]);
            float hx = __bfloat162float(__float2bfloat16_rn(v.x));
            float hy = __bfloat162float(__float2bfloat16_rn(v.y));
            float hz = __bfloat162float(__float2bfloat16_rn(v.z));
            float hw = __bfloat162float(__float2bfloat16_rn(v.w));
            int o = kk * WST + (n4 >> 1);
            wsh[o]     = pack_bf2(v.x, v.y);
            wsh[o + 1] = pack_bf2(v.z, v.w);
            wsl[o]     = pack_bf2(v.x - hx, v.y - hy);
            wsl[o + 1] = pack_bf2(v.z - hz, v.w - hw);
        }
        __syncthreads();

        #pragma unroll
        for (int h = 0; h < 32; h += 16) {
            unsigned ah[4][4], al[4][4];
            #pragma unroll
            for (int mt = 0; mt < 4; mt++) {
                unsigned off = a_off + (mt * 16 * AST * 2 + h) * 2;
                LDSM_X4(ah[mt], a_hi_base + off);
                LDSM_X4(al[mt], a_lo_base + off);
            }
            unsigned bh4[4], bl4[4];
            {
                unsigned off = w_off + (h * WST * 2) * 2;
                LDSM_X4_T(bh4, w_hi_base + off);
                LDSM_X4_T(bl4, w_lo_base + off);
            }
            #pragma unroll
            for (int mt = 0; mt < 4; mt++) {
                #pragma unroll
                for (int nt = 0; nt < 2; nt++) {
                    unsigned bh[2] = {bh4[nt * 2], bh4[nt * 2 + 1]};
                    unsigned bl[2] = {bl4[nt * 2], bl4[nt * 2 + 1]};
                    MMA_BF16(acc[mt][nt], ah[mt], bh);
                    MMA_BF16(acc[mt][nt], ah[mt], bl);
                    MMA_BF16(acc[mt][nt], al[mt], bh);
                }
            }
        }
        __syncthreads();
    }

    int g = lane >> 2, tig = lane & 3;
    #pragma unroll
    for (int mt = 0; mt < 4; mt++) {
        #pragma unroll
        for (int nt = 0; nt < 2; nt++) {
            int n = wn * 16 + nt * 8 + tig * 2;
            int ml0 = m0 + wm * 64 + mt * 16 + g;
            float* c0 = acc[mt][nt];
            *reinterpret_cast<float2*>(&Op[ml0 * 64 + n])       = make_float2(c0[0], c0[1]);
            *reinterpret_cast<float2*>(&Op[(ml0 + 8) * 64 + n]) = make_float2(c0[2], c0[3]);
        }
    }
}

// ---------- combination matrices: g_C[mat] = (s0*W0 + s1*W1 + s2*W2) @ Wc_part^T ----------
__global__ void cmat_kernel(const float* __restrict__ W, const float* __restrict__ Wc) {
    __shared__ float wc[40 * 257];
    int mat = blockIdx.y;     // 0..6
    int strip = blockIdx.x;   // 0..7
    int tid = threadIdx.x;
    int part;
    float s0, s1, s2;
    switch (mat) {
        case 0:  part = 1; s0 =  1.f; s1 = 0.f;  s2 = -1.f; break;  // B0i - B2i
        case 1:  part = 0; s0 = -1.f; s1 = 0.f;  s2 =  1.f; break;  // -(B0r - B2r)
        case 2:  part = 1; s0 =  0.f; s1 = 1.f;  s2 =  0.f; break;  // B1i
        case 3:  part = 0; s0 =  0.f; s1 = -1.f; s2 =  0.f; break;  // -B1r
        case 4:  part = 1; s0 =  0.f; s1 = 0.f;  s2 =  1.f; break;  // B2i
        case 5:  part = 0; s0 =  0.f; s1 = 0.f;  s2 = -1.f; break;  // -B2r
        default: part = 0; s0 =  0.f; s1 = 0.f;  s2 =  1.f; break;  // B2r
    }
    for (int idx = tid; idx < 40 * 256; idx += 256) {
        int c = idx >> 8, f = idx & 255;
        wc[c * 257 + f] = Wc[c * 512 + part * 256 + f];
    }
    __syncthreads();
    int a = strip * 32 + (tid >> 3);
    int cg = tid & 7;
    float acc[5] = {0.f, 0.f, 0.f, 0.f, 0.f};
    for (int f = 0; f < 256; f++) {
        float w = 0.f;
        if (s0 != 0.f) w += s0 * W[a * 256 + f];
        if (s1 != 0.f) w += s1 * W[65536 + a * 256 + f];
        if (s2 != 0.f) w += s2 * W[131072 + a * 256 + f];
        #pragma unroll
        for (int j = 0; j < 5; j++)
            acc[j] = fmaf(w, wc[(cg * 5 + j) * 257 + f], acc[j]);
    }
    #pragma unroll
    for (int j = 0; j < 5; j++)
        g_C[mat][a * 64 + cg * 5 + j] = acc[j];
    // zero pad cols 40..63 for this strip
    for (int idx = tid; idx < 32 * 24; idx += 256) {
        int r = idx / 24, c = 40 + idx % 24;
        g_C[mat][(strip * 32 + r) * 64 + c] = 0.f;
    }
}

__global__ void cvec_kernel(const float* __restrict__ b2, const float* __restrict__ Wc) {
    int c = threadIdx.x;   // 64 threads
    if (c >= 64) return;
    float s = 0.f;
    if (c < 40)
        for (int f = 0; f < 256; f++)
            s += b2[f] * (Wc[c * 512 + f] + Wc[c * 512 + 256 + f]);
    g_cvec[c] = s;
}

__global__ void sumv_kernel() {
    int i = blockIdx.x * blockDim.x + threadIdx.x;   // 262144
    g_Vre[i] = g_Vp[0][i] + g_Vp[1][i];
    g_Vim[i] = g_Vp[2][i] + g_Vp[3][i];
}

// ---------- final: logits = sum(Dp) + 2T + cvec + bc -> log_softmax ----------
__global__ void final_kernel(const float* __restrict__ bc, float* __restrict__ out) {
    int warp = threadIdx.x >> 5, lane = threadIdx.x & 31;
    int row = blockIdx.x * 8 + warp;
    float a = -3.4e38f, b = -3.4e38f;
    if (lane < 40) {
        int o = row * 64 + lane;
        a = g_Dp[0][o] + g_Dp[1][o] + g_Dp[2][o] + g_Dp[3][o]
          + 2.f * g_T[o] + g_cvec[lane] + bc[lane];
    }
    if (lane + 32 < 40) {
        int o = row * 64 + lane + 32;
        b = g_Dp[0][o] + g_Dp[1][o] + g_Dp[2][o] + g_Dp[3][o]
          + 2.f * g_T[o] + g_cvec[lane + 32] + bc[lane + 32];
    }
    float m = fmaxf(a, b);
    #pragma unroll
    for (int o = 16; o > 0; o >>= 1) m = fmaxf(m, __shfl_xor_sync(0xffffffffu, m, o));
    float s = ((lane < 40) ? expf(a - m) : 0.f) + ((lane + 32 < 40) ? expf(b - m) : 0.f);
    #pragma unroll
    for (int o = 16; o > 0; o >>= 1) s += __shfl_xor_sync(0xffffffffu, s, o);
    float lse = m + logf(s);
    if (lane < 40)      out[row * 40 + lane]      = a - lse;
    if (lane + 32 < 40) out[row * 40 + lane + 32] = b - lse;
}

// ---------------- launch ----------------
extern "C" void kernel_launch(void* const* d_in, const int* in_sizes, int n_in,
                              void* d_out, int out_size) {
    const float* real = (const float*)d_in[0];
    const float* imag = (const float*)d_in[1];
    const int*   edges = (const int*)d_in[2];
    const float* qp = (const float*)d_in[3];
    const float* ew = (const float*)d_in[4];
    const float* W1 = (const float*)d_in[5];
    const float* b1 = (const float*)d_in[6];
    const float* W2 = (const float*)d_in[7];
    const float* b2 = (const float*)d_in[8];
    const float* Wc = (const float*)d_in[9];
    const float* bc = (const float*)d_in[10];
    float* out = (float*)d_out;
    int E = in_sizes[4];

    float *Z1r, *Z1i, *Z2r, *Z2i, *H1r, *H1i, *Cbase, *Dpbase, *Vpbase;
    cudaGetSymbolAddress((void**)&Z1r, g_Z1r);
    cudaGetSymbolAddress((void**)&Z1i, g_Z1i);
    cudaGetSymbolAddress((void**)&Z2r, g_Z2r);
    cudaGetSymbolAddress((void**)&Z2i, g_Z2i);
    cudaGetSymbolAddress((void**)&H1r, g_H1r);
    cudaGetSymbolAddress((void**)&H1i, g_H1i);
    cudaGetSymbolAddress((void**)&Cbase, g_C);
    cudaGetSymbolAddress((void**)&Dpbase, g_Dp);
    cudaGetSymbolAddress((void**)&Vpbase, g_Vp);
    float *Vre, *Vim, *T;
    cudaGetSymbolAddress((void**)&Vre, g_Vre);
    cudaGetSymbolAddress((void**)&Vim, g_Vim);
    cudaGetSymbolAddress((void**)&T,   g_T);

    // graph build + classifier-fold constants (independent of activations)
    zero_kernel<<<TSIZE / 256, 256>>>();
    insert_kernel<<<(E + 255) / 256, 256>>>(edges, ew, E);
    dinv_kernel<<<NN / 256, 256>>>();
    emit_kernel<<<TSIZE / 256, 256>>>(qp);
    cmat_kernel<<<dim3(8, 7), 256>>>(W2, Wc);
    cvec_kernel<<<1, 64>>>(b2, Wc);

    // ---- layer 1 (unchanged, full-width) ----
    spmm_kernel<<<NN, 256>>>(real, imag, nullptr, nullptr, Z1r, Z1i);
    spmm_kernel<<<NN, 256>>>(Z1r, Z1i, real, imag, Z2r, Z2i);
    gemm_fused_kernel<<<dim3(4, 64), 256>>>(real, Z1r, Z2r, imag, Z1i, Z2i, W1, b1, H1r, H1i);

    // ---- layer 2 folded into classifier ----
    spmm_kernel<<<NN, 256>>>(H1r, H1i, nullptr, nullptr, Z1r, Z1i);   // Z1 = L H1

    PPArgs pp;
    pp.A[0] = H1r; pp.C[0] = Cbase + 0 * 16384; pp.O[0] = Dpbase + 0 * (NN * 64);
    pp.A[1] = H1i; pp.C[1] = Cbase + 1 * 16384; pp.O[1] = Dpbase + 1 * (NN * 64);
    pp.A[2] = Z1r; pp.C[2] = Cbase + 2 * 16384; pp.O[2] = Dpbase + 2 * (NN * 64);
    pp.A[3] = Z1i; pp.C[3] = Cbase + 3 * 16384; pp.O[3] = Dpbase + 3 * (NN * 64);
    pp.A[4] = Z1r; pp.C[4] = Cbase + 4 * 16384; pp.O[4] = Vpbase + 0 * (NN * 64);
    pp.A[5] = Z1i; pp.C[5] = Cbase + 5 * 16384; pp.O[5] = Vpbase + 1 * (NN * 64);
    pp.A[6] = Z1r; pp.C[6] = Cbase + 6 * 16384; pp.O[6] = Vpbase + 2 * (NN * 64);
    pp.A[7] = Z1i; pp.C[7] = Cbase + 4 * 16384; pp.O[7] = Vpbase + 3 * (NN * 64);
    planeprod_kernel<<<dim3(8, 32), 256>>>(pp);

    sumv_kernel<<<(NN * 64) / 256, 256>>>();
    spmm64_kernel<<<NN, 64>>>(Vre, Vim, T);
    final_kernel<<<NN / 8, 256>>>(bc, out);
}

// round 14
// speedup vs baseline: 1.3605x; 1.0181x over previous
#include <cuda_runtime.h>
#include <cuda_bf16.h>
#include <math.h>

#define NN   4096
#define FF   256
#define ELLW 256
#define TBITS 19
#define TSIZE (1 << TBITS)
#define TMASK (TSIZE - 1)

// ---------------- scratch (device globals) ----------------
__device__ int   g_hkey[TSIZE];
__device__ float g_hvalF[TSIZE];
__device__ float g_hvalR[TSIZE];
__device__ float g_deg[NN];
__device__ float g_dinv[NN];
__device__ int   g_cnt[NN];
__device__ int4  g_ell[NN * ELLW];   // AoS: {col, lre_bits, lim_bits, pad}
__device__ float g_Z1r[NN * FF], g_Z1i[NN * FF];
__device__ float g_Z2r[NN * FF], g_Z2i[NN * FF];
__device__ float g_H1r[NN * FF], g_H1i[NN * FF];
// layer-2 folded-classifier scratch (all 4096x64)
__device__ float g_C[8][256 * 64];     // combination matrices
__device__ float g_cvec[64];
__device__ float g_D0[NN * 64];
__device__ float g_U1re[NN * 64], g_U1im[NN * 64];
__device__ float g_U2re[NN * 64], g_U2im[NN * 64];
__device__ float g_Vre[NN * 64],  g_Vim[NN * 64];
__device__ float g_T1[NN * 64],   g_T2[NN * 64];

__device__ __forceinline__ unsigned hash_key(int key) {
    return ((unsigned)key * 2654435761u) >> (32 - TBITS);
}

// ---------------- graph build (R13-proven) ----------------
__global__ void zero_kernel() {
    int idx = blockIdx.x * blockDim.x + threadIdx.x;
    if (idx < TSIZE) { g_hkey[idx] = -1; g_hvalF[idx] = 0.f; g_hvalR[idx] = 0.f; }
    if (idx < NN)    { g_deg[idx] = 0.f; g_cnt[idx] = 0; }
}

__global__ void insert_kernel(const int* __restrict__ edges,
                              const float* __restrict__ w, int E) {
    int e = blockIdx.x * blockDim.x + threadIdx.x;
    if (e >= E) return;
    int r = edges[e];
    int c = edges[E + e];
    float we = w[e];
    atomicAdd(&g_deg[r], 0.5f * we);
    atomicAdd(&g_deg[c], 0.5f * we);
    int lo = min(r, c), hi = max(r, c);
    int key = (lo << 12) | hi;
    unsigned h = hash_key(key) & TMASK;
    while (true) {
        int prev = atomicCAS(&g_hkey[h], -1, key);
        if (prev == -1 || prev == key) {
            if (r <= c) atomicAdd(&g_hvalF[h], we);
            else        atomicAdd(&g_hvalR[h], we);
            break;
        }
        h = (h + 1) & TMASK;
    }
}

__global__ void dinv_kernel() {
    int i = blockIdx.x * blockDim.x + threadIdx.x;
    if (i < NN) {
        float d = g_deg[i];
        if (d == 0.f) d = 1.f;
        g_dinv[i] = rsqrtf(d);
    }
}

__device__ __forceinline__ void ell_push(int r, int c, float lre, float lim) {
    int slot = atomicAdd(&g_cnt[r], 1);
    if (slot < ELLW) {
        g_ell[r * ELLW + slot] =
            make_int4(c, __float_as_int(lre), __float_as_int(lim), 0);
    }
}

__global__ void emit_kernel(const float* __restrict__ qp) {
    int s = blockIdx.x * blockDim.x + threadIdx.x;
    if (s >= TSIZE) return;
    int key = g_hkey[s];
    if (key < 0) return;
    int i = key >> 12;         // i <= j
    int j = key & 4095;
    float F = g_hvalF[s];
    float R = g_hvalR[s];
    float q = __ldg(qp);
    if (i == j) {
        float di = g_dinv[i];
        ell_push(i, i, -di * di * F, 0.f);
        return;
    }
    float asym = 0.5f * (F + R);
    float an = g_dinv[i] * asym * g_dinv[j];
    float th = 6.283185307179586f * q * (F - R);
    float sn, cs;
    __sincosf(th, &sn, &cs);
    ell_push(i, j, -an * cs,  an * sn);
    ell_push(j, i, -an * cs, -an * sn);
}

// ---------------- complex SpMM (ELL, AoS), full width (R13-proven) ----------------
__global__ void spmm_kernel(const float* __restrict__ Xr, const float* __restrict__ Xi,
                            const float* __restrict__ Sr, const float* __restrict__ Si,
                            float* __restrict__ Yr, float* __restrict__ Yi) {
    int row = blockIdx.x;
    int t = threadIdx.x;
    int cnt = g_cnt[row];
    if (cnt > ELLW) cnt = ELLW;
    __shared__ int   sc[ELLW];
    __shared__ float slr[ELLW];
    __shared__ float sli[ELLW];
    for (int k = t; k < cnt; k += 256) {
        int4 v = g_ell[row * ELLW + k];
        sc [k] = v.x;
        slr[k] = __int_as_float(v.y);
        sli[k] = __int_as_float(v.z);
    }
    __syncthreads();
    float ar = 0.f, ai = 0.f;
    #pragma unroll 4
    for (int k = 0; k < cnt; k++) {
        int   c  = sc[k];
        float lr = slr[k];
        float li = sli[k];
        float xr = __ldg(&Xr[c * FF + t]);
        float xi = __ldg(&Xi[c * FF + t]);
        ar = fmaf(lr, xr, ar);
        ar = fmaf(-li, xi, ar);
        ai = fmaf(lr, xi, ai);
        ai = fmaf(li, xr, ai);
    }
    int o = row * FF + t;
    if (Sr) {
        Yr[o] = 2.f * ar - Sr[o];
        Yi[o] = 2.f * ai - Si[o];
    } else {
        Yr[o] = ar;
        Yi[o] = ai;
    }
}

// ---------------- narrow spmm pass A: V = L U2 (complex) ; T1 = Re(L U1) ----------------
__global__ void spmmA_kernel() {
    int row = blockIdx.x;
    int t = threadIdx.x;   // 64
    int cnt = g_cnt[row];
    if (cnt > ELLW) cnt = ELLW;
    __shared__ int   sc[ELLW];
    __shared__ float slr[ELLW];
    __shared__ float sli[ELLW];
    for (int k = t; k < cnt; k += 64) {
        int4 v = g_ell[row * ELLW + k];
        sc [k] = v.x;
        slr[k] = __int_as_float(v.y);
        sli[k] = __int_as_float(v.z);
    }
    __syncthreads();
    float vr = 0.f, vi = 0.f, t1 = 0.f;
    #pragma unroll 4
    for (int k = 0; k < cnt; k++) {
        int c = sc[k];
        float lr = slr[k];
        float li = sli[k];
        float u2r = __ldg(&g_U2re[c * 64 + t]);
        float u2i = __ldg(&g_U2im[c * 64 + t]);
        float u1r = __ldg(&g_U1re[c * 64 + t]);
        float u1i = __ldg(&g_U1im[c * 64 + t]);
        vr = fmaf(lr, u2r, vr); vr = fmaf(-li, u2i, vr);
        vi = fmaf(lr, u2i, vi); vi = fmaf(li, u2r, vi);
        t1 = fmaf(lr, u1r, t1); t1 = fmaf(-li, u1i, t1);
    }
    int o = row * 64 + t;
    g_Vre[o] = vr;
    g_Vim[o] = vi;
    g_T1[o] = t1;
}

// ---------------- narrow spmm pass B: T2 = Re(L V) ----------------
__global__ void spmmB_kernel() {
    int row = blockIdx.x;
    int t = threadIdx.x;   // 64
    int cnt = g_cnt[row];
    if (cnt > ELLW) cnt = ELLW;
    __shared__ int   sc[ELLW];
    __shared__ float slr[ELLW];
    __shared__ float sli[ELLW];
    for (int k = t; k < cnt; k += 64) {
        int4 v = g_ell[row * ELLW + k];
        sc [k] = v.x;
        slr[k] = __int_as_float(v.y);
        sli[k] = __int_as_float(v.z);
    }
    __syncthreads();
    float acc = 0.f;
    #pragma unroll 4
    for (int k = 0; k < cnt; k++) {
        int c = sc[k];
        acc = fmaf(slr[k],  __ldg(&g_Vre[c * 64 + t]), acc);
        acc = fmaf(-sli[k], __ldg(&g_Vim[c * 64 + t]), acc);
    }
    g_T2[row * 64 + t] = acc;
}

// ---------------- GEMM machinery (proven) ----------------
__device__ __forceinline__ unsigned pack_bf2(float x, float y) {
    __nv_bfloat162 t;
    t.x = __float2bfloat16_rn(x);
    t.y = __float2bfloat16_rn(y);
    return *reinterpret_cast<unsigned*>(&t);
}

#define MMA_BF16(d, a, b)                                                        \
    asm volatile("mma.sync.aligned.m16n8k16.row.col.f32.bf16.bf16.f32 "          \
                 "{%0,%1,%2,%3},{%4,%5,%6,%7},{%8,%9},{%0,%1,%2,%3};"            \
                 : "+f"(d[0]), "+f"(d[1]), "+f"(d[2]), "+f"(d[3])                 \
                 : "r"(a[0]), "r"(a[1]), "r"(a[2]), "r"(a[3]), "r"(b[0]), "r"(b[1]))

#define LDSM_X4(r, addr)                                                         \
    asm volatile("ldmatrix.sync.aligned.m8n8.x4.shared.b16 {%0,%1,%2,%3}, [%4];" \
                 : "=r"(r[0]), "=r"(r[1]), "=r"(r[2]), "=r"(r[3]) : "r"(addr) : "memory")

#define LDSM_X4_T(r, addr)                                                             \
    asm volatile("ldmatrix.sync.aligned.m8n8.x4.trans.shared.b16 {%0,%1,%2,%3}, [%4];" \
                 : "=r"(r[0]), "=r"(r[1]), "=r"(r[2]), "=r"(r[3]) : "r"(addr) : "memory")

#define AST 20
#define WST 36

// ---------- layer-1 fused GEMM (proven, verbatim) ----------
__global__ void __launch_bounds__(256, 2)
gemm_fused_kernel(const float* __restrict__ A0r, const float* __restrict__ A1r,
                  const float* __restrict__ A2r, const float* __restrict__ A0i,
                  const float* __restrict__ A1i, const float* __restrict__ A2i,
                  const float* __restrict__ W, const float* __restrict__ bias,
                  float* __restrict__ Hr, float* __restrict__ Hi) {
    __shared__ unsigned ash[128 * AST], asl[128 * AST];
    __shared__ unsigned wsh[32 * WST],  wsl[32 * WST];

    int tid = threadIdx.x;
    int lane = tid & 31;
    int warp = tid >> 5;
    int wm = warp >> 2;
    int wn = warp & 3;
    int m0 = blockIdx.y * 128;
    int n0 = blockIdx.x * 64;
    bool isImag = (m0 >= 4096);
    int mrow0 = m0 & 4095;

    float acc[4][2][4];
    #pragma unroll
    for (int mt = 0; mt < 4; mt++)
        #pragma unroll
        for (int nt = 0; nt < 2; nt++)
            #pragma unroll
            for (int r = 0; r < 4; r++) acc[mt][nt][r] = 0.f;

    unsigned a_hi_base = (unsigned)__cvta_generic_to_shared(ash);
    unsigned a_lo_base = (unsigned)__cvta_generic_to_shared(asl);
    unsigned w_hi_base = (unsigned)__cvta_generic_to_shared(wsh);
    unsigned w_lo_base = (unsigned)__cvta_generic_to_shared(wsl);

    unsigned a_off = ((wm * 64 + (lane & 15)) * (AST * 2) + (lane >> 4) * 8) * 2;
    unsigned w_off = (((((lane >> 3) & 1) * 8 + (lane & 7)) * (WST * 2)) + wn * 16 + (lane >> 4) * 8) * 2;

    for (int ks = 0; ks < 24; ks++) {
        int k0 = ks * 32;
        int plane = k0 >> 8;
        int kc = k0 & 255;
        const float* Ap = isImag ? (plane == 0 ? A0i : (plane == 1 ? A1i : A2i))
                                 : (plane == 0 ? A0r : (plane == 1 ? A1r : A2r));
        #pragma unroll
        for (int t = 0; t < 4; t++) {
            int idx = tid + t * 256;
            int r = idx >> 3;
            int c4 = (idx & 7) * 4;
            float4 v = *reinterpret_cast<const float4*>(&Ap[(mrow0 + r) * 256 + kc + c4]);
            float hx = __bfloat162float(__float2bfloat16_rn(v.x));
            float hy = __bfloat162float(__float2bfloat16_rn(v.y));
            float hz = __bfloat162float(__float2bfloat16_rn(v.z));
            float hw = __bfloat162float(__float2bfloat16_rn(v.w));
            int o = r * AST + (c4 >> 1);
            ash[o]     = pack_bf2(v.x, v.y);
            ash[o + 1] = pack_bf2(v.z, v.w);
            asl[o]     = pack_bf2(v.x - hx, v.y - hy);
            asl[o + 1] = pack_bf2(v.z - hz, v.w - hw);
        }
        #pragma unroll
        for (int t = 0; t < 2; t++) {
            int idx = tid + t * 256;
            int kk = idx >> 4;
            int n4 = (idx & 15) * 4;
            float4 v = *reinterpret_cast<const float4*>(&W[plane * 65536 + (kc + kk) * 256 + n0 + n4]);
            float hx = __bfloat162float(__float2bfloat16_rn(v.x));
            float hy = __bfloat162float(__float2bfloat16_rn(v.y));
            float hz = __bfloat162float(__float2bfloat16_rn(v.z));
            float hw = __bfloat162float(__float2bfloat16_rn(v.w));
            int o = kk * WST + (n4 >> 1);
            wsh[o]     = pack_bf2(v.x, v.y);
            wsh[o + 1] = pack_bf2(v.z, v.w);
            wsl[o]     = pack_bf2(v.x - hx, v.y - hy);
            wsl[o + 1] = pack_bf2(v.z - hz, v.w - hw);
        }
        __syncthreads();

        #pragma unroll
        for (int h = 0; h < 32; h += 16) {
            unsigned ah[4][4], al[4][4];
            #pragma unroll
            for (int mt = 0; mt < 4; mt++) {
                unsigned off = a_off + (mt * 16 * AST * 2 + h) * 2;
                LDSM_X4(ah[mt], a_hi_base + off);
                LDSM_X4(al[mt], a_lo_base + off);
            }
            unsigned bh4[4], bl4[4];
            {
                unsigned off = w_off + (h * WST * 2) * 2;
                LDSM_X4_T(bh4, w_hi_base + off);
                LDSM_X4_T(bl4, w_lo_base + off);
            }
            #pragma unroll
            for (int mt = 0; mt < 4; mt++) {
                #pragma unroll
                for (int nt = 0; nt < 2; nt++) {
                    unsigned bh[2] = {bh4[nt * 2], bh4[nt * 2 + 1]};
                    unsigned bl[2] = {bl4[nt * 2], bl4[nt * 2 + 1]};
                    MMA_BF16(acc[mt][nt], ah[mt], bh);
                    MMA_BF16(acc[mt][nt], ah[mt], bl);
                    MMA_BF16(acc[mt][nt], al[mt], bh);
                }
            }
        }
        __syncthreads();
    }

    int g = lane >> 2, tig = lane & 3;
    #pragma unroll
    for (int mt = 0; mt < 4; mt++) {
        #pragma unroll
        for (int nt = 0; nt < 2; nt++) {
            int n = n0 + wn * 16 + nt * 8 + tig * 2;
            float b0 = bias[n], b1v = bias[n + 1];
            int ml0 = mrow0 + wm * 64 + mt * 16 + g;
            float* c0 = acc[mt][nt];
            if (!isImag) {
                float2 o0 = make_float2(c0[0] + b0, c0[1] + b1v);
                float2 o1 = make_float2(c0[2] + b0, c0[3] + b1v);
                *reinterpret_cast<float2*>(&Hi[ml0 * 256 + n])       = o0;
                *reinterpret_cast<float2*>(&Hi[(ml0 + 8) * 256 + n]) = o1;
            } else {
                float2 o0 = make_float2(-c0[0] + b0, -c0[1] + b1v);
                float2 o1 = make_float2(-c0[2] + b0, -c0[3] + b1v);
                *reinterpret_cast<float2*>(&Hr[ml0 * 256 + n])       = o0;
                *reinterpret_cast<float2*>(&Hr[(ml0 + 8) * 256 + n]) = o1;
            }
        }
    }
}

// ---------- dual plane products: O[j] = A0[j]@C0[j] + A1[j]@C1[j]  (K=256 each) ----------
struct PP2Args {
    const float* A0[5];
    const float* C0[5];
    const float* A1[5];
    const float* C1[5];
    float* O[5];
};

__global__ void __launch_bounds__(256, 2)
planeprod2_kernel(PP2Args pp) {
    __shared__ unsigned ash[128 * AST], asl[128 * AST];
    __shared__ unsigned wsh[32 * WST],  wsl[32 * WST];

    int tid = threadIdx.x;
    int lane = tid & 31;
    int warp = tid >> 5;
    int wm = warp >> 2;
    int wn = warp & 3;
    int p = blockIdx.x;
    int m0 = blockIdx.y * 128;
    float* Op = pp.O[p];

    float acc[4][2][4];
    #pragma unroll
    for (int mt = 0; mt < 4; mt++)
        #pragma unroll
        for (int nt = 0; nt < 2; nt++)
            #pragma unroll
            for (int r = 0; r < 4; r++) acc[mt][nt][r] = 0.f;

    unsigned a_hi_base = (unsigned)__cvta_generic_to_shared(ash);
    unsigned a_lo_base = (unsigned)__cvta_generic_to_shared(asl);
    unsigned w_hi_base = (unsigned)__cvta_generic_to_shared(wsh);
    unsigned w_lo_base = (unsigned)__cvta_generic_to_shared(wsl);

    unsigned a_off = ((wm * 64 + (lane & 15)) * (AST * 2) + (lane >> 4) * 8) * 2;
    unsigned w_off = (((((lane >> 3) & 1) * 8 + (lane & 7)) * (WST * 2)) + wn * 16 + (lane >> 4) * 8) * 2;

    for (int ks = 0; ks < 16; ks++) {
        int plane = ks >> 3;
        int kc = (ks & 7) * 32;
        const float* Ap = plane ? pp.A1[p] : pp.A0[p];
        const float* Cm = plane ? pp.C1[p] : pp.C0[p];
        // A tile 128x32
        #pragma unroll
        for (int t = 0; t < 4; t++) {
            int idx = tid + t * 256;
            int r = idx >> 3;
            int c4 = (idx & 7) * 4;
            float4 v = *reinterpret_cast<const float4*>(&Ap[(m0 + r) * 256 + kc + c4]);
            float hx = __bfloat162float(__float2bfloat16_rn(v.x));
            float hy = __bfloat162float(__float2bfloat16_rn(v.y));
            float hz = __bfloat162float(__float2bfloat16_rn(v.z));
            float hw = __bfloat162float(__float2bfloat16_rn(v.w));
            int o = r * AST + (c4 >> 1);
            ash[o]     = pack_bf2(v.x, v.y);
            ash[o + 1] = pack_bf2(v.z, v.w);
            asl[o]     = pack_bf2(v.x - hx, v.y - hy);
            asl[o + 1] = pack_bf2(v.z - hz, v.w - hw);
        }
        // C tile 32x64 (pitch 64)
        #pragma unroll
        for (int t = 0; t < 2; t++) {
            int idx = tid + t * 256;
            int kk = idx >> 4;
            int n4 = (idx & 15) * 4;
            float4 v = *reinterpret_cast<const float4*>(&Cm[(kc + kk) * 64 + n4]);
            float hx = __bfloat162float(__float2bfloat16_rn(v.x));
            float hy = __bfloat162float(__float2bfloat16_rn(v.y));
            float hz = __bfloat162float(__float2bfloat16_rn(v.z));
            float hw = __bfloat162float(__float2bfloat16_rn(v.w));
            int o = kk * WST + (n4 >> 1);
            wsh[o]     = pack_bf2(v.x, v.y);
            wsh[o + 1] = pack_bf2(v.z, v.w);
            wsl[o]     = pack_bf2(v.x - hx, v.y - hy);
            wsl[o + 1] = pack_bf2(v.z - hz, v.w - hw);
        }
        __syncthreads();

        #pragma unroll
        for (int h = 0; h < 32; h += 16) {
            unsigned ah[4][4], al[4][4];
            #pragma unroll
            for (int mt = 0; mt < 4; mt++) {
                unsigned off = a_off + (mt * 16 * AST * 2 + h) * 2;
                LDSM_X4(ah[mt], a_hi_base + off);
                LDSM_X4(al[mt], a_lo_base + off);
            }
            unsigned bh4[4], bl4[4];
            {
                unsigned off = w_off + (h * WST * 2) * 2;
                LDSM_X4_T(bh4, w_hi_base + off);
                LDSM_X4_T(bl4, w_lo_base + off);
            }
            #pragma unroll
            for (int mt = 0; mt < 4; mt++) {
                #pragma unroll
                for (int nt = 0; nt < 2; nt++) {
                    unsigned bh[2] = {bh4[nt * 2], bh4[nt * 2 + 1]};
                    unsigned bl[2] = {bl4[nt * 2], bl4[nt * 2 + 1]};
                    MMA_BF16(acc[mt][nt], ah[mt], bh);
                    MMA_BF16(acc[mt][nt], ah[mt], bl);
                    MMA_BF16(acc[mt][nt], al[mt], bh);
                }
            }
        }
        __syncthreads();
    }

    int g = lane >> 2, tig = lane & 3;
    #pragma unroll
    for (int mt = 0; mt < 4; mt++) {
        #pragma unroll
        for (int nt = 0; nt < 2; nt++) {
            int n = wn * 16 + nt * 8 + tig * 2;
            int ml0 = m0 + wm * 64 + mt * 16 + g;
            float* c0 = acc[mt][nt];
            *reinterpret_cast<float2*>(&Op[ml0 * 64 + n])       = make_float2(c0[0], c0[1]);
            *reinterpret_cast<float2*>(&Op[(ml0 + 8) * 64 + n]) = make_float2(c0[2], c0[3]);
        }
    }
}

// ---------- combination matrices ----------
// mats: 0:(B0i-B2i) 1:-(B0r-B2r) 2:B1i 3:-B1r 4:B2i 5:-B2r 6:B2r 7:B1r
// Bki = W2[k] @ Wci^T, Bkr = W2[k] @ Wcr^T   (padded to 64 cols with zeros)
__global__ void cmat_kernel(const float* __restrict__ W, const float* __restrict__ Wc) {
    __shared__ float wc[40 * 257];
    int mat = blockIdx.y;     // 0..7
    int strip = blockIdx.x;   // 0..7
    int tid = threadIdx.x;
    int part;
    float s0, s1, s2;
    switch (mat) {
        case 0:  part = 1; s0 =  1.f; s1 = 0.f;  s2 = -1.f; break;
        case 1:  part = 0; s0 = -1.f; s1 = 0.f;  s2 =  1.f; break;
        case 2:  part = 1; s0 =  0.f; s1 = 1.f;  s2 =  0.f; break;
        case 3:  part = 0; s0 =  0.f; s1 = -1.f; s2 =  0.f; break;
        case 4:  part = 1; s0 =  0.f; s1 = 0.f;  s2 =  1.f; break;
        case 5:  part = 0; s0 =  0.f; s1 = 0.f;  s2 = -1.f; break;
        case 6:  part = 0; s0 =  0.f; s1 = 0.f;  s2 =  1.f; break;
        default: part = 0; s0 =  0.f; s1 = 1.f;  s2 =  0.f; break;
    }
    for (int idx = tid; idx < 40 * 256; idx += 256) {
        int c = idx >> 8, f = idx & 255;
        wc[c * 257 + f] = Wc[c * 512 + part * 256 + f];
    }
    __syncthreads();
    int a = strip * 32 + (tid >> 3);
    int cg = tid & 7;
    float acc[5] = {0.f, 0.f, 0.f, 0.f, 0.f};
    for (int f = 0; f < 256; f++) {
        float w = 0.f;
        if (s0 != 0.f) w += s0 * W[a * 256 + f];
        if (s1 != 0.f) w += s1 * W[65536 + a * 256 + f];
        if (s2 != 0.f) w += s2 * W[131072 + a * 256 + f];
        #pragma unroll
        for (int j = 0; j < 5; j++)
            acc[j] = fmaf(w, wc[(cg * 5 + j) * 257 + f], acc[j]);
    }
    #pragma unroll
    for (int j = 0; j < 5; j++)
        g_C[mat][a * 64 + cg * 5 + j] = acc[j];
    for (int idx = tid; idx < 32 * 24; idx += 256) {
        int r = idx / 24, c = 40 + idx % 24;
        g_C[mat][(strip * 32 + r) * 64 + c] = 0.f;
    }
}

__global__ void cvec_kernel(const float* __restrict__ b2, const float* __restrict__ Wc) {
    int c = threadIdx.x;   // 64 threads
    if (c >= 64) return;
    float s = 0.f;
    if (c < 40)
        for (int f = 0; f < 256; f++)
            s += b2[f] * (Wc[c * 512 + f] + Wc[c * 512 + 256 + f]);
    g_cvec[c] = s;
}

// ---------- final: logits = D0 + T1 + 2*T2 + cvec + bc -> log_softmax ----------
__global__ void final_kernel(const float* __restrict__ bc, float* __restrict__ out) {
    int warp = threadIdx.x >> 5, lane = threadIdx.x & 31;
    int row = blockIdx.x * 8 + warp;
    float a = -3.4e38f, b = -3.4e38f;
    if (lane < 40) {
        int o = row * 64 + lane;
        a = g_D0[o] + g_T1[o] + 2.f * g_T2[o] + g_cvec[lane] + bc[lane];
    }
    if (lane + 32 < 40) {
        int o = row * 64 + lane + 32;
        b = g_D0[o] + g_T1[o] + 2.f * g_T2[o] + g_cvec[lane + 32] + bc[lane + 32];
    }
    float m = fmaxf(a, b);
    #pragma unroll
    for (int o = 16; o > 0; o >>= 1) m = fmaxf(m, __shfl_xor_sync(0xffffffffu, m, o));
    float s = ((lane < 40) ? expf(a - m) : 0.f) + ((lane + 32 < 40) ? expf(b - m) : 0.f);
    #pragma unroll
    for (int o = 16; o > 0; o >>= 1) s += __shfl_xor_sync(0xffffffffu, s, o);
    float lse = m + logf(s);
    if (lane < 40)      out[row * 40 + lane]      = a - lse;
    if (lane + 32 < 40) out[row * 40 + lane + 32] = b - lse;
}

// ---------------- launch ----------------
extern "C" void kernel_launch(void* const* d_in, const int* in_sizes, int n_in,
                              void* d_out, int out_size) {
    const float* real = (const float*)d_in[0];
    const float* imag = (const float*)d_in[1];
    const int*   edges = (const int*)d_in[2];
    const float* qp = (const float*)d_in[3];
    const float* ew = (const float*)d_in[4];
    const float* W1 = (const float*)d_in[5];
    const float* b1 = (const float*)d_in[6];
    const float* W2 = (const float*)d_in[7];
    const float* b2 = (const float*)d_in[8];
    const float* Wc = (const float*)d_in[9];
    const float* bc = (const float*)d_in[10];
    float* out = (float*)d_out;
    int E = in_sizes[4];

    float *Z1r, *Z1i, *Z2r, *Z2i, *H1r, *H1i, *Cbase;
    float *D0, *U1re, *U1im, *U2re, *U2im;
    cudaGetSymbolAddress((void**)&Z1r, g_Z1r);
    cudaGetSymbolAddress((void**)&Z1i, g_Z1i);
    cudaGetSymbolAddress((void**)&Z2r, g_Z2r);
    cudaGetSymbolAddress((void**)&Z2i, g_Z2i);
    cudaGetSymbolAddress((void**)&H1r, g_H1r);
    cudaGetSymbolAddress((void**)&H1i, g_H1i);
    cudaGetSymbolAddress((void**)&Cbase, g_C);
    cudaGetSymbolAddress((void**)&D0,   g_D0);
    cudaGetSymbolAddress((void**)&U1re, g_U1re);
    cudaGetSymbolAddress((void**)&U1im, g_U1im);
    cudaGetSymbolAddress((void**)&U2re, g_U2re);
    cudaGetSymbolAddress((void**)&U2im, g_U2im);

    // graph build + classifier-fold constants
    zero_kernel<<<TSIZE / 256, 256>>>();
    insert_kernel<<<(E + 255) / 256, 256>>>(edges, ew, E);
    dinv_kernel<<<NN / 256, 256>>>();
    emit_kernel<<<TSIZE / 256, 256>>>(qp);
    cmat_kernel<<<dim3(8, 8), 256>>>(W2, Wc);
    cvec_kernel<<<1, 64>>>(b2, Wc);

    // ---- layer 1 (full-width) ----
    spmm_kernel<<<NN, 256>>>(real, imag, nullptr, nullptr, Z1r, Z1i);
    spmm_kernel<<<NN, 256>>>(Z1r, Z1i, real, imag, Z2r, Z2i);
    gemm_fused_kernel<<<dim3(4, 64), 256>>>(real, Z1r, Z2r, imag, Z1i, Z2i, W1, b1, H1r, H1i);

    // ---- layer 2 fully folded: no full-width spmm ----
    PP2Args pp;
    // D0   = H1r(B0i-B2i) + H1i(-(B0r-B2r))
    pp.A0[0] = H1r; pp.C0[0] = Cbase + 0 * 16384; pp.A1[0] = H1i; pp.C1[0] = Cbase + 1 * 16384; pp.O[0] = D0;
    // U1re = H1r B1i + H1i (-B1r)
    pp.A0[1] = H1r; pp.C0[1] = Cbase + 2 * 16384; pp.A1[1] = H1i; pp.C1[1] = Cbase + 3 * 16384; pp.O[1] = U1re;
    // U1im = H1r B1r + H1i B1i
    pp.A0[2] = H1r; pp.C0[2] = Cbase + 7 * 16384; pp.A1[2] = H1i; pp.C1[2] = Cbase + 2 * 16384; pp.O[2] = U1im;
    // U2re = H1r B2i + H1i (-B2r)
    pp.A0[3] = H1r; pp.C0[3] = Cbase + 4 * 16384; pp.A1[3] = H1i; pp.C1[3] = Cbase + 5 * 16384; pp.O[3] = U2re;
    // U2im = H1r B2r + H1i B2i
    pp.A0[4] = H1r; pp.C0[4] = Cbase + 6 * 16384; pp.A1[4] = H1i; pp.C1[4] = Cbase + 4 * 16384; pp.O[4] = U2im;
    planeprod2_kernel<<<dim3(5, 32), 256>>>(pp);

    spmmA_kernel<<<NN, 64>>>();   // V = L U2 (complex), T1 = Re(L U1)
    spmmB_kernel<<<NN, 64>>>();   // T2 = Re(L V)
    final_kernel<<<NN / 8, 256>>>(bc, out);
}